// round 11
// baseline (speedup 1.0000x reference)
#include <cuda_runtime.h>
#include <cuda_bf16.h>
#include <cstdint>
#include <cstddef>

// Problem constants
#define BATCH 8
#define NSEQ  1032          // 32*32 + 8
#define NSEQP 1088          // padded to 17*64
#define CDIM  768
#define HEADS 12
#define HD    64
#define MROWS (BATCH*NSEQ)  // 8256
#define KVW   1536          // k+v columns
#define K2    2304          // triple-block K (3*768): A=[hi|hi|lo], B=[hi|lo|hi]
#define NPANEL (BATCH*HEADS) // 96

// Device scratch (static globals — zero-initialized, no runtime allocation).
__device__ float g_kv[(size_t)MROWS * KVW];          // K|V fp32
__device__ __nv_bfloat16 g_xc  [(size_t)MROWS * K2]; // x       A-type [hi|hi|lo]
__device__ __nv_bfloat16 g_attc[(size_t)MROWS * K2]; // attnout A-type [hi|hi|lo] (written by attn epilogue)
__device__ __nv_bfloat16 g_wkv [(size_t)KVW   * K2]; // qkv_w rows 768.. B-type [hi|lo|hi]
__device__ __nv_bfloat16 g_wprj[(size_t)CDIM  * K2]; // proj_w B-type [hi|lo|hi]
__device__ __nv_bfloat16 g_kc[(size_t)NPANEL * NSEQP * 128];    // per (b,h): [j][K_hi(64)|K_lo(64)]
__device__ __nv_bfloat16 g_vt[(size_t)NPANEL * 64 * 2 * NSEQP]; // per (b,h): [d][Vt_hi(NSEQP)|Vt_lo(NSEQP)]

// ---------------------------------------------------------------------------
// Helpers (portable PTX: ldmatrix / mma.sync / cp.async)
// ---------------------------------------------------------------------------
__device__ __forceinline__ uint32_t smem_u32(const void* p) {
    uint32_t a;
    asm("{ .reg .u64 t; cvta.to.shared.u64 t, %1; cvt.u32.u64 %0, t; }" : "=r"(a) : "l"(p));
    return a;
}
#define SMEM_SWIZZLE_128B(x) ((x) ^ (((x) >> 3) & 0x70))

#define CP_ASYNC16(sa, ga) \
    asm volatile("cp.async.cg.shared.global [%0], [%1], 16;" :: "r"(sa), "l"(ga) : "memory")
#define CP_COMMIT() asm volatile("cp.async.commit_group;" ::: "memory")
#define CP_WAIT1()  asm volatile("cp.async.wait_group 1;" ::: "memory")
#define CP_WAIT0()  asm volatile("cp.async.wait_group 0;" ::: "memory")

__device__ __forceinline__ void ldsm_x4(uint32_t* r, uint32_t addr) {
    asm volatile("ldmatrix.sync.aligned.m8n8.x4.shared.b16 {%0,%1,%2,%3}, [%4];"
                 : "=r"(r[0]), "=r"(r[1]), "=r"(r[2]), "=r"(r[3]) : "r"(addr));
}

__device__ __forceinline__ void mma_16816(float* c, const uint32_t* a,
                                          uint32_t b0, uint32_t b1) {
    asm volatile("mma.sync.aligned.m16n8k16.row.col.f32.bf16.bf16.f32 "
                 "{%0,%1,%2,%3}, {%4,%5,%6,%7}, {%8,%9}, {%0,%1,%2,%3};"
                 : "+f"(c[0]), "+f"(c[1]), "+f"(c[2]), "+f"(c[3])
                 : "r"(a[0]), "r"(a[1]), "r"(a[2]), "r"(a[3]), "r"(b0), "r"(b1));
}

// ---------------------------------------------------------------------------
// Triple-block conversion for projection GEMM operands.
//   A-type (which 0): x -> g_xc  [hi | hi | lo]
//   B-type (which 2,3): weights -> [hi | lo | hi]
// ---------------------------------------------------------------------------
__global__ __launch_bounds__(256) void conv_dual_kernel(
    const float* __restrict__ src, int which, int R, int K, int srow_off)
{
    __nv_bfloat16* dst = (which == 0) ? g_xc : (which == 2) ? g_wkv : g_wprj;
    const bool atype = (which == 0);

    size_t total4 = (size_t)R * K / 4;
    size_t idx = (size_t)blockIdx.x * blockDim.x + threadIdx.x;
    if (idx >= total4) return;
    int kq = (int)(idx % (K / 4));
    int r  = (int)(idx / (K / 4));
    float4 v = *(const float4*)(src + (size_t)(srow_off + r) * K + kq * 4);
    __nv_bfloat16 h0 = __float2bfloat16(v.x);
    __nv_bfloat16 h1 = __float2bfloat16(v.y);
    __nv_bfloat16 h2 = __float2bfloat16(v.z);
    __nv_bfloat16 h3 = __float2bfloat16(v.w);
    __nv_bfloat16 l0 = __float2bfloat16(v.x - __bfloat162float(h0));
    __nv_bfloat16 l1 = __float2bfloat16(v.y - __bfloat162float(h1));
    __nv_bfloat16 l2 = __float2bfloat16(v.z - __bfloat162float(h2));
    __nv_bfloat16 l3 = __float2bfloat16(v.w - __bfloat162float(h3));

    __nv_bfloat16* d0 = dst + (size_t)r * K2 + kq * 4;
    __nv_bfloat16* d1 = d0 + K;
    __nv_bfloat16* d2 = d0 + 2 * K;
    d0[0] = h0; d0[1] = h1; d0[2] = h2; d0[3] = h3;
    if (atype) {
        d1[0] = h0; d1[1] = h1; d1[2] = h2; d1[3] = h3;
        d2[0] = l0; d2[1] = l1; d2[2] = l2; d2[3] = l3;
    } else {
        d1[0] = l0; d1[1] = l1; d1[2] = l2; d1[3] = l3;
        d2[0] = h0; d2[1] = h1; d2[2] = h2; d2[3] = h3;
    }
}

// ---------------------------------------------------------------------------
// K/V panel conversion: g_kv fp32 -> g_kc (K hi|lo) + g_vt (V^T hi|lo)
// ---------------------------------------------------------------------------
__global__ __launch_bounds__(256) void conv_kv_kernel()
{
    __shared__ float vt[64][65];
    const int tid = threadIdx.x;
    const int bh = blockIdx.y, b = bh / HEADS, h = bh % HEADS;
    const int j0 = blockIdx.x * 64;

#pragma unroll
    for (int it = 0; it < 16; it++) {
        int idx = tid + 256 * it;
        int j = idx >> 6, d = idx & 63;
        int gj = j0 + j;
        float vvv = 0.0f;
        if (gj < NSEQ) {
            const float* src = g_kv + ((size_t)b * NSEQ + gj) * KVW + h * HD;
            float kvv = src[d];
            vvv = src[CDIM + d];
            __nv_bfloat16 hi = __float2bfloat16(kvv);
            __nv_bfloat16 lo = __float2bfloat16(kvv - __bfloat162float(hi));
            __nv_bfloat16* dst = g_kc + ((size_t)bh * NSEQP + gj) * 128;
            dst[d] = hi; dst[64 + d] = lo;
        }
        vt[j][d] = vvv;
    }
    __syncthreads();
#pragma unroll
    for (int it = 0; it < 16; it++) {
        int idx = tid + 256 * it;
        int d = idx >> 6, j = idx & 63;
        int gj = j0 + j;
        if (gj < NSEQ) {
            float v = vt[j][d];
            __nv_bfloat16 hi = __float2bfloat16(v);
            __nv_bfloat16 lo = __float2bfloat16(v - __bfloat162float(hi));
            __nv_bfloat16* dst = g_vt + ((size_t)bh * 64 + d) * (2 * NSEQP);
            dst[gj] = hi; dst[NSEQP + gj] = lo;
        }
    }
}

// ---------------------------------------------------------------------------
// HMMA GEMM over K2=2304 (core verified R9/R10). Now __launch_bounds__(256,2)
// to lift occupancy from 1 CTA/SM (134 regs) to 2 CTAs/SM.
// ---------------------------------------------------------------------------
#define GEMM_SMEM 65536

__global__ __launch_bounds__(256, 2) void gemm_mma_kernel(
    int which, const float* __restrict__ bias, float* __restrict__ outp)
{
    extern __shared__ __align__(128) char smem[];
    const uint32_t sb = smem_u32(smem);

    const __nv_bfloat16* __restrict__ A  = which ? g_attc : g_xc;
    const __nv_bfloat16* __restrict__ Bw = which ? g_wprj : g_wkv;
    float* C = which ? outp : g_kv;
    const int N = which ? CDIM : KVW;

    const int tid  = threadIdx.x;
    const int lane = tid & 31;
    const int w    = tid >> 5;
    const int wm   = w >> 2;
    const int wn   = w & 3;
    const int n0   = blockIdx.x * 128;
    const int m0   = blockIdx.y * 128;

    float acc[4][4][4];
#pragma unroll
    for (int mi = 0; mi < 4; mi++)
#pragma unroll
        for (int ni = 0; ni < 4; ni++)
#pragma unroll
            for (int c = 0; c < 4; c++) acc[mi][ni][c] = 0.0f;

    const int srow = tid >> 3;
    const int q    = tid & 7;

    auto issue_stage = [&](int ch, int buf) {
        const uint32_t sa_base = sb + (uint32_t)buf * 32768u;
        const uint32_t sb_base = sa_base + 16384u;
#pragma unroll
        for (int u = 0; u < 4; u++) {
            const int row = srow + 32 * u;
            int am = m0 + row; if (am > MROWS - 1) am = MROWS - 1;
            const uint32_t so = SMEM_SWIZZLE_128B((uint32_t)(row * 128 + q * 16));
            CP_ASYNC16(sa_base + so, A  + (size_t)am * K2 + ch * 64 + q * 8);
            CP_ASYNC16(sb_base + so, Bw + (size_t)(n0 + row) * K2 + ch * 64 + q * 8);
        }
        CP_COMMIT();
    };

    const int NSTAGE = K2 / 64;      // 36
    issue_stage(0, 0);

    for (int ch = 0; ch < NSTAGE; ch++) {
        const int buf = ch & 1;
        if (ch + 1 < NSTAGE) { issue_stage(ch + 1, buf ^ 1); CP_WAIT1(); }
        else                 { CP_WAIT0(); }
        __syncthreads();

        const uint32_t abase = sb + (uint32_t)buf * 32768u;
        const uint32_t bbase = abase + 16384u;
        const int rsel = lane & 15;
        const int chi  = lane >> 4;

#pragma unroll
        for (int kk = 0; kk < 4; kk++) {
            const int c8 = kk * 2 + chi;
            uint32_t af[4][4], bfr[2][4];
#pragma unroll
            for (int mi = 0; mi < 4; mi++) {
                const int row = wm * 64 + mi * 16 + rsel;
                ldsm_x4(af[mi], abase + SMEM_SWIZZLE_128B((uint32_t)(row * 128 + c8 * 16)));
            }
#pragma unroll
            for (int g = 0; g < 2; g++) {
                const int row = wn * 32 + g * 16 + rsel;
                ldsm_x4(bfr[g], bbase + SMEM_SWIZZLE_128B((uint32_t)(row * 128 + c8 * 16)));
            }
#pragma unroll
            for (int mi = 0; mi < 4; mi++)
#pragma unroll
                for (int ni = 0; ni < 4; ni++) {
                    const int g = ni >> 1, o = ni & 1;
                    mma_16816(acc[mi][ni], af[mi], bfr[g][o], bfr[g][o + 2]);
                }
        }
        __syncthreads();
    }

#pragma unroll
    for (int mi = 0; mi < 4; mi++) {
        const int r0 = m0 + wm * 64 + mi * 16 + (lane >> 2);
        const int r1 = r0 + 8;
#pragma unroll
        for (int ni = 0; ni < 4; ni++) {
            const int col = n0 + wn * 32 + ni * 8 + (lane & 3) * 2;
            const float b0v = bias[col], b1v = bias[col + 1];
            if (r0 < MROWS) {
                float2 v = make_float2(acc[mi][ni][0] + b0v, acc[mi][ni][1] + b1v);
                *(float2*)(C + (size_t)r0 * N + col) = v;
            }
            if (r1 < MROWS) {
                float2 v = make_float2(acc[mi][ni][2] + b0v, acc[mi][ni][3] + b1v);
                *(float2*)(C + (size_t)r1 * N + col) = v;
            }
        }
    }
}

// ---------------------------------------------------------------------------
// Tensor-core flash attention, double-buffered j-tiles.
// CTA = (b,h) x 128 i-rows, 8 warps x (16 rows x 64 cols).
// Epilogue writes triple-block g_attc directly (no fp32 round trip).
// Smem: Ki hi/lo 32KB | 2 j-stages x 32KB | P hi/lo 32KB | ftab.
// ---------------------------------------------------------------------------
#define AK_KI_HI 0
#define AK_KI_LO 16384
#define AK_STG(t)  (32768 + (t) * 32768)   // in stage: KJ_HI+0 KJ_LO+8192 VT_HI+16384 VT_LO+24576
#define AK_P_HI  98304
#define AK_P_LO  114688
#define AK_FTAB  131072
#define AK_SMEM  (131072 + 256)

__global__ __launch_bounds__(256) void attn_mma_kernel()
{
    extern __shared__ __align__(128) char sm[];
    const uint32_t sb = smem_u32(sm);
    float* ftab = (float*)(sm + AK_FTAB);

    const int tid = threadIdx.x, lane = tid & 31, w = tid >> 5;
    const int bh = blockIdx.y, b = bh / HEADS, h = bh % HEADS;
    const int i0 = blockIdx.x * 128;

    if (tid < 63) { float xx = (float)tid - 31.0f; ftab[tid] = __expf(-xx * xx * 0.02f); }

    const int srow = tid >> 3, q = tid & 7;

    auto issue_jtile = [&](int jt, int t) {
        const uint32_t stg = sb + AK_STG(t);
#pragma unroll
        for (int u = 0; u < 2; u++) {
            int row = srow + 32 * u;
            const __nv_bfloat16* sk = g_kc + ((size_t)bh * NSEQP + jt + row) * 128 + q * 8;
            const __nv_bfloat16* sv = g_vt + ((size_t)bh * 64 + row) * (2 * NSEQP) + jt + q * 8;
            uint32_t so = SMEM_SWIZZLE_128B((uint32_t)(row * 128 + q * 16));
            CP_ASYNC16(stg +         so, sk);          // KJ_HI
            CP_ASYNC16(stg + 8192u + so, sk + 64);     // KJ_LO
            CP_ASYNC16(stg + 16384u + so, sv);         // VT_HI
            CP_ASYNC16(stg + 24576u + so, sv + NSEQP); // VT_LO
        }
        CP_COMMIT();
    };

    // Prologue: Ki (hi/lo) + first j-tile in flight
    {
#pragma unroll
        for (int u = 0; u < 4; u++) {
            int row = srow + 32 * u;
            int gi = i0 + row; if (gi > NSEQ - 1) gi = NSEQ - 1;
            const __nv_bfloat16* src = g_kc + ((size_t)bh * NSEQP + gi) * 128 + q * 8;
            uint32_t so = SMEM_SWIZZLE_128B((uint32_t)(row * 128 + q * 16));
            CP_ASYNC16(sb + AK_KI_HI + so, src);
            CP_ASYNC16(sb + AK_KI_LO + so, src + 64);
        }
        CP_COMMIT();
        issue_jtile(0, 0);
    }

    const int rsel = lane & 15, chi = lane >> 4;
    const int rA = w * 16 + (lane >> 2);
    const int iA = i0 + rA, iB = iA + 8;
    const bool okA = (iA >= 8) && (iA < NSEQ);
    const bool okB = (iB >= 8) && (iB < NSEQ);
    const int qiA1 = (iA - 8) >> 5, qiA2 = (iA - 8) & 31;
    const int qiB1 = (iB - 8) >> 5, qiB2 = (iB - 8) & 31;

    float mA = -1e30f, mB = -1e30f, lA = 0.0f, lB = 0.0f;
    float O[8][4];
#pragma unroll
    for (int ni = 0; ni < 8; ni++)
#pragma unroll
        for (int c = 0; c < 4; c++) O[ni][c] = 0.0f;

    const float scale = 0.125f;

    for (int jt = 0; jt < NSEQP; jt += 64) {
        const int t = (jt >> 6) & 1;
        // All outstanding loads (this tile; prologue also Ki) complete + visible.
        // This barrier also guarantees all warps are done computing tile jt-64,
        // so issuing tile jt+64 into the other stage below is race-free.
        CP_WAIT0();
        __syncthreads();
        if (jt + 64 < NSEQP) issue_jtile(jt + 64, t ^ 1);

        const uint32_t stg = sb + AK_STG(t);

        // ---- S = Ki.Kj^T: passes (hi,hi),(hi,lo),(lo,hi) ----
        float s[8][4];
#pragma unroll
        for (int ni = 0; ni < 8; ni++)
#pragma unroll
            for (int c = 0; c < 4; c++) s[ni][c] = 0.0f;

        const uint32_t apass[3] = {sb + AK_KI_HI, sb + AK_KI_HI, sb + AK_KI_LO};
        const uint32_t bpass[3] = {stg, stg + 8192u, stg};
#pragma unroll
        for (int ps = 0; ps < 3; ps++) {
#pragma unroll
            for (int kk = 0; kk < 4; kk++) {
                const int c8 = kk * 2 + chi;
                uint32_t af[4], bfr[4][4];
                ldsm_x4(af, apass[ps] +
                        SMEM_SWIZZLE_128B((uint32_t)((w * 16 + rsel) * 128 + c8 * 16)));
#pragma unroll
                for (int g = 0; g < 4; g++)
                    ldsm_x4(bfr[g], bpass[ps] +
                            SMEM_SWIZZLE_128B((uint32_t)((g * 16 + rsel) * 128 + c8 * 16)));
#pragma unroll
                for (int ni = 0; ni < 8; ni++)
                    mma_16816(s[ni], af, bfr[ni >> 1][ni & 1], bfr[ni >> 1][(ni & 1) + 2]);
            }
        }

        // ---- scale + gaussian bias + tail mask ----
#pragma unroll
        for (int ni = 0; ni < 8; ni++) {
            const int jbase = jt + ni * 8 + ((lane & 3) << 1);
#pragma unroll
            for (int c = 0; c < 4; c++) {
                const int j = jbase + (c & 1);
                float val = s[ni][c] * scale;
                const bool ok = (c < 2) ? okA : okB;
                const int q1 = (c < 2) ? qiA1 : qiB1;
                const int q2 = (c < 2) ? qiA2 : qiB2;
                if (j < NSEQ) {
                    if (ok && j >= 8)
                        val += ftab[q1 - ((j - 8) >> 5) + 31] * ftab[q2 - ((j - 8) & 31) + 31];
                } else val = -1e30f;
                s[ni][c] = val;
            }
        }

        // ---- online softmax ----
        float tA = -1e30f, tB = -1e30f;
#pragma unroll
        for (int ni = 0; ni < 8; ni++) {
            tA = fmaxf(tA, fmaxf(s[ni][0], s[ni][1]));
            tB = fmaxf(tB, fmaxf(s[ni][2], s[ni][3]));
        }
        tA = fmaxf(tA, __shfl_xor_sync(0xffffffffu, tA, 1));
        tA = fmaxf(tA, __shfl_xor_sync(0xffffffffu, tA, 2));
        tB = fmaxf(tB, __shfl_xor_sync(0xffffffffu, tB, 1));
        tB = fmaxf(tB, __shfl_xor_sync(0xffffffffu, tB, 2));
        const float mnA = fmaxf(mA, tA), mnB = fmaxf(mB, tB);
        const float cA = __expf(mA - mnA), cB = __expf(mB - mnB);
        float rsA = 0.0f, rsB = 0.0f;
#pragma unroll
        for (int ni = 0; ni < 8; ni++) {
            s[ni][0] = __expf(s[ni][0] - mnA); rsA += s[ni][0];
            s[ni][1] = __expf(s[ni][1] - mnA); rsA += s[ni][1];
            s[ni][2] = __expf(s[ni][2] - mnB); rsB += s[ni][2];
            s[ni][3] = __expf(s[ni][3] - mnB); rsB += s[ni][3];
        }
        rsA += __shfl_xor_sync(0xffffffffu, rsA, 1);
        rsA += __shfl_xor_sync(0xffffffffu, rsA, 2);
        rsB += __shfl_xor_sync(0xffffffffu, rsB, 1);
        rsB += __shfl_xor_sync(0xffffffffu, rsB, 2);
        lA = lA * cA + rsA; lB = lB * cB + rsB;
        mA = mnA; mB = mnB;

        // ---- P -> smem (hi/lo, warp-private rows) + O rescale ----
        const uint32_t rowoffA = (uint32_t)((w * 16 + (lane >> 2)) * 128 + (lane & 3) * 4);
        const uint32_t rowoffB = rowoffA + 8 * 128;
#pragma unroll
        for (int ni = 0; ni < 8; ni++) {
            O[ni][0] *= cA; O[ni][1] *= cA; O[ni][2] *= cB; O[ni][3] *= cB;

            __nv_bfloat16 h0 = __float2bfloat16(s[ni][0]);
            __nv_bfloat16 h1 = __float2bfloat16(s[ni][1]);
            __nv_bfloat162 hv; hv.x = h0; hv.y = h1;
            __nv_bfloat162 lv;
            lv.x = __float2bfloat16(s[ni][0] - __bfloat162float(h0));
            lv.y = __float2bfloat16(s[ni][1] - __bfloat162float(h1));
            const uint32_t offA = SMEM_SWIZZLE_128B(rowoffA + ni * 16);
            *(__nv_bfloat162*)(sm + AK_P_HI + offA) = hv;
            *(__nv_bfloat162*)(sm + AK_P_LO + offA) = lv;

            __nv_bfloat16 h2 = __float2bfloat16(s[ni][2]);
            __nv_bfloat16 h3 = __float2bfloat16(s[ni][3]);
            __nv_bfloat162 hv2; hv2.x = h2; hv2.y = h3;
            __nv_bfloat162 lv2;
            lv2.x = __float2bfloat16(s[ni][2] - __bfloat162float(h2));
            lv2.y = __float2bfloat16(s[ni][3] - __bfloat162float(h3));
            const uint32_t offB = SMEM_SWIZZLE_128B(rowoffB + ni * 16);
            *(__nv_bfloat162*)(sm + AK_P_HI + offB) = hv2;
            *(__nv_bfloat162*)(sm + AK_P_LO + offB) = lv2;
        }
        __syncwarp();

        // ---- O += P.V: passes (P_hi,V_hi),(P_hi,V_lo),(P_lo,V_hi) ----
        const uint32_t papass[3] = {sb + AK_P_HI, sb + AK_P_HI, sb + AK_P_LO};
        const uint32_t vbpass[3] = {stg + 16384u, stg + 24576u, stg + 16384u};
#pragma unroll
        for (int ps = 0; ps < 3; ps++) {
#pragma unroll
            for (int kk = 0; kk < 4; kk++) {
                const int c8 = kk * 2 + chi;
                uint32_t af[4], bfr[4][4];
                ldsm_x4(af, papass[ps] +
                        SMEM_SWIZZLE_128B((uint32_t)((w * 16 + rsel) * 128 + c8 * 16)));
#pragma unroll
                for (int g = 0; g < 4; g++)
                    ldsm_x4(bfr[g], vbpass[ps] +
                            SMEM_SWIZZLE_128B((uint32_t)((g * 16 + rsel) * 128 + c8 * 16)));
#pragma unroll
                for (int ni = 0; ni < 8; ni++)
                    mma_16816(O[ni], af, bfr[ni >> 1][ni & 1], bfr[ni >> 1][(ni & 1) + 2]);
            }
        }
    }

    // ---- epilogue: normalize, write triple-block g_attc directly ----
    const float invA = 1.0f / lA, invB = 1.0f / lB;
#pragma unroll
    for (int ni = 0; ni < 8; ni++) {
        const int d = ni * 8 + ((lane & 3) << 1);
        if (iA < NSEQ) {
            float v0 = O[ni][0] * invA, v1 = O[ni][1] * invA;
            __nv_bfloat162 hv, lv;
            hv.x = __float2bfloat16(v0); hv.y = __float2bfloat16(v1);
            lv.x = __float2bfloat16(v0 - __bfloat162float(hv.x));
            lv.y = __float2bfloat16(v1 - __bfloat162float(hv.y));
            __nv_bfloat16* dst = g_attc + (size_t)(b * NSEQ + iA) * K2 + h * HD + d;
            *(__nv_bfloat162*)(dst)            = hv;
            *(__nv_bfloat162*)(dst + CDIM)     = hv;
            *(__nv_bfloat162*)(dst + 2 * CDIM) = lv;
        }
        if (iB < NSEQ) {
            float v0 = O[ni][2] * invB, v1 = O[ni][3] * invB;
            __nv_bfloat162 hv, lv;
            hv.x = __float2bfloat16(v0); hv.y = __float2bfloat16(v1);
            lv.x = __float2bfloat16(v0 - __bfloat162float(hv.x));
            lv.y = __float2bfloat16(v1 - __bfloat162float(hv.y));
            __nv_bfloat16* dst = g_attc + (size_t)(b * NSEQ + iB) * K2 + h * HD + d;
            *(__nv_bfloat162*)(dst)            = hv;
            *(__nv_bfloat162*)(dst + CDIM)     = hv;
            *(__nv_bfloat162*)(dst + 2 * CDIM) = lv;
        }
    }
}

// ---------------------------------------------------------------------------
extern "C" void kernel_launch(void* const* d_in, const int* in_sizes, int n_in,
                              void* d_out, int out_size)
{
    const float* x = nullptr;
    const float* qkv_w = nullptr;
    const float* qkv_b = nullptr;
    const float* proj_w = nullptr;
    const float* proj_b = nullptr;
    for (int i = 0; i < n_in; i++) {
        switch (in_sizes[i]) {
            case 6340608: x      = (const float*)d_in[i]; break;
            case 1769472: qkv_w  = (const float*)d_in[i]; break;
            case 2304:    qkv_b  = (const float*)d_in[i]; break;
            case 589824:  proj_w = (const float*)d_in[i]; break;
            case 768:     proj_b = (const float*)d_in[i]; break;
        }
    }
    float* out = (float*)d_out;

    cudaFuncSetAttribute(gemm_mma_kernel, cudaFuncAttributeMaxDynamicSharedMemorySize, GEMM_SMEM);
    cudaFuncSetAttribute(attn_mma_kernel, cudaFuncAttributeMaxDynamicSharedMemorySize, AK_SMEM);

    // conversions: x, W_kv, W_proj -> triple-block bf16
    {
        size_t t4 = (size_t)MROWS * CDIM / 4;
        conv_dual_kernel<<<(unsigned)((t4 + 255) / 256), 256>>>(x, 0, MROWS, CDIM, 0);
        t4 = (size_t)KVW * CDIM / 4;
        conv_dual_kernel<<<(unsigned)((t4 + 255) / 256), 256>>>(qkv_w, 2, KVW, CDIM, CDIM);
        t4 = (size_t)CDIM * CDIM / 4;
        conv_dual_kernel<<<(unsigned)((t4 + 255) / 256), 256>>>(proj_w, 3, CDIM, CDIM, 0);
    }
    // 1) K,V projection via HMMA -> g_kv (fp32)
    {
        dim3 grid(KVW / 128, (MROWS + 127) / 128);   // 12 x 65
        gemm_mma_kernel<<<grid, 256, GEMM_SMEM>>>(0, qkv_b + CDIM, nullptr);
    }
    // 2) K/V panel conversion (hi/lo bf16, V transposed)
    {
        dim3 grid(17, NPANEL);                       // 17 x 96
        conv_kv_kernel<<<grid, 256>>>();
    }
    // 3) tensor-core flash attention -> g_attc (triple-block, direct)
    {
        dim3 grid((NSEQ + 127) / 128, NPANEL);       // 9 x 96
        attn_mma_kernel<<<grid, 256, AK_SMEM>>>();
    }
    // 4) output projection via HMMA -> d_out
    {
        dim3 grid(CDIM / 128, (MROWS + 127) / 128);  // 6 x 65
        gemm_mma_kernel<<<grid, 256, GEMM_SMEM>>>(1, proj_b, out);
    }
}

// round 12
// speedup vs baseline: 1.0500x; 1.0500x over previous
#include <cuda_runtime.h>
#include <cuda_bf16.h>
#include <cstdint>
#include <cstddef>

// Problem constants
#define BATCH 8
#define NSEQ  1032          // 32*32 + 8
#define NSEQP 1088          // padded to 17*64
#define CDIM  768
#define HEADS 12
#define HD    64
#define MROWS (BATCH*NSEQ)  // 8256
#define KVW   1536          // k+v columns
#define K2    2304          // triple-block K (3*768): A=[hi|hi|lo], B=[hi|lo|hi]
#define NPANEL (BATCH*HEADS) // 96

// Device scratch (static globals — zero-initialized, no runtime allocation).
__device__ float g_kv[(size_t)MROWS * KVW];          // K|V fp32
__device__ __nv_bfloat16 g_xc  [(size_t)MROWS * K2]; // x       A-type [hi|hi|lo]
__device__ __nv_bfloat16 g_attc[(size_t)MROWS * K2]; // attnout A-type [hi|hi|lo] (written by attn epilogue)
__device__ __nv_bfloat16 g_wkv [(size_t)KVW   * K2]; // qkv_w rows 768.. B-type [hi|lo|hi]
__device__ __nv_bfloat16 g_wprj[(size_t)CDIM  * K2]; // proj_w B-type [hi|lo|hi]
__device__ __nv_bfloat16 g_kc[(size_t)NPANEL * NSEQP * 128];    // per (b,h): [j][K_hi(64)|K_lo(64)]
__device__ __nv_bfloat16 g_vt[(size_t)NPANEL * 64 * 2 * NSEQP]; // per (b,h): [d][Vt_hi(NSEQP)|Vt_lo(NSEQP)]

// ---------------------------------------------------------------------------
// Helpers (portable PTX: ldmatrix / mma.sync / cp.async)
// ---------------------------------------------------------------------------
__device__ __forceinline__ uint32_t smem_u32(const void* p) {
    uint32_t a;
    asm("{ .reg .u64 t; cvta.to.shared.u64 t, %1; cvt.u32.u64 %0, t; }" : "=r"(a) : "l"(p));
    return a;
}
#define SMEM_SWIZZLE_128B(x) ((x) ^ (((x) >> 3) & 0x70))

#define CP_ASYNC16(sa, ga) \
    asm volatile("cp.async.cg.shared.global [%0], [%1], 16;" :: "r"(sa), "l"(ga) : "memory")
#define CP_COMMIT() asm volatile("cp.async.commit_group;" ::: "memory")
#define CP_WAIT1()  asm volatile("cp.async.wait_group 1;" ::: "memory")
#define CP_WAIT0()  asm volatile("cp.async.wait_group 0;" ::: "memory")

__device__ __forceinline__ void ldsm_x4(uint32_t* r, uint32_t addr) {
    asm volatile("ldmatrix.sync.aligned.m8n8.x4.shared.b16 {%0,%1,%2,%3}, [%4];"
                 : "=r"(r[0]), "=r"(r[1]), "=r"(r[2]), "=r"(r[3]) : "r"(addr));
}

__device__ __forceinline__ void mma_16816(float* c, const uint32_t* a,
                                          uint32_t b0, uint32_t b1) {
    asm volatile("mma.sync.aligned.m16n8k16.row.col.f32.bf16.bf16.f32 "
                 "{%0,%1,%2,%3}, {%4,%5,%6,%7}, {%8,%9}, {%0,%1,%2,%3};"
                 : "+f"(c[0]), "+f"(c[1]), "+f"(c[2]), "+f"(c[3])
                 : "r"(a[0]), "r"(a[1]), "r"(a[2]), "r"(a[3]), "r"(b0), "r"(b1));
}

// ---------------------------------------------------------------------------
// Triple-block conversion for projection GEMM operands.
// ---------------------------------------------------------------------------
__global__ __launch_bounds__(256) void conv_dual_kernel(
    const float* __restrict__ src, int which, int R, int K, int srow_off)
{
    __nv_bfloat16* dst = (which == 0) ? g_xc : (which == 2) ? g_wkv : g_wprj;
    const bool atype = (which == 0);

    size_t total4 = (size_t)R * K / 4;
    size_t idx = (size_t)blockIdx.x * blockDim.x + threadIdx.x;
    if (idx >= total4) return;
    int kq = (int)(idx % (K / 4));
    int r  = (int)(idx / (K / 4));
    float4 v = *(const float4*)(src + (size_t)(srow_off + r) * K + kq * 4);
    __nv_bfloat16 h0 = __float2bfloat16(v.x);
    __nv_bfloat16 h1 = __float2bfloat16(v.y);
    __nv_bfloat16 h2 = __float2bfloat16(v.z);
    __nv_bfloat16 h3 = __float2bfloat16(v.w);
    __nv_bfloat16 l0 = __float2bfloat16(v.x - __bfloat162float(h0));
    __nv_bfloat16 l1 = __float2bfloat16(v.y - __bfloat162float(h1));
    __nv_bfloat16 l2 = __float2bfloat16(v.z - __bfloat162float(h2));
    __nv_bfloat16 l3 = __float2bfloat16(v.w - __bfloat162float(h3));

    __nv_bfloat16* d0 = dst + (size_t)r * K2 + kq * 4;
    __nv_bfloat16* d1 = d0 + K;
    __nv_bfloat16* d2 = d0 + 2 * K;
    d0[0] = h0; d0[1] = h1; d0[2] = h2; d0[3] = h3;
    if (atype) {
        d1[0] = h0; d1[1] = h1; d1[2] = h2; d1[3] = h3;
        d2[0] = l0; d2[1] = l1; d2[2] = l2; d2[3] = l3;
    } else {
        d1[0] = l0; d1[1] = l1; d1[2] = l2; d1[3] = l3;
        d2[0] = h0; d2[1] = h1; d2[2] = h2; d2[3] = h3;
    }
}

// ---------------------------------------------------------------------------
// K/V panel conversion: g_kv fp32 -> g_kc (K hi|lo) + g_vt (V^T hi|lo)
// ---------------------------------------------------------------------------
__global__ __launch_bounds__(256) void conv_kv_kernel()
{
    __shared__ float vt[64][65];
    const int tid = threadIdx.x;
    const int bh = blockIdx.y, b = bh / HEADS, h = bh % HEADS;
    const int j0 = blockIdx.x * 64;

#pragma unroll
    for (int it = 0; it < 16; it++) {
        int idx = tid + 256 * it;
        int j = idx >> 6, d = idx & 63;
        int gj = j0 + j;
        float vvv = 0.0f;
        if (gj < NSEQ) {
            const float* src = g_kv + ((size_t)b * NSEQ + gj) * KVW + h * HD;
            float kvv = src[d];
            vvv = src[CDIM + d];
            __nv_bfloat16 hi = __float2bfloat16(kvv);
            __nv_bfloat16 lo = __float2bfloat16(kvv - __bfloat162float(hi));
            __nv_bfloat16* dst = g_kc + ((size_t)bh * NSEQP + gj) * 128;
            dst[d] = hi; dst[64 + d] = lo;
        }
        vt[j][d] = vvv;
    }
    __syncthreads();
#pragma unroll
    for (int it = 0; it < 16; it++) {
        int idx = tid + 256 * it;
        int d = idx >> 6, j = idx & 63;
        int gj = j0 + j;
        if (gj < NSEQ) {
            float v = vt[j][d];
            __nv_bfloat16 hi = __float2bfloat16(v);
            __nv_bfloat16 lo = __float2bfloat16(v - __bfloat162float(hi));
            __nv_bfloat16* dst = g_vt + ((size_t)bh * 64 + d) * (2 * NSEQP);
            dst[gj] = hi; dst[NSEQP + gj] = lo;
        }
    }
}

// ---------------------------------------------------------------------------
// HMMA GEMM over K2=2304 (verified; 2 CTAs/SM via launch_bounds(256,2)).
// ---------------------------------------------------------------------------
#define GEMM_SMEM 65536

__global__ __launch_bounds__(256, 2) void gemm_mma_kernel(
    int which, const float* __restrict__ bias, float* __restrict__ outp)
{
    extern __shared__ __align__(128) char smem[];
    const uint32_t sb = smem_u32(smem);

    const __nv_bfloat16* __restrict__ A  = which ? g_attc : g_xc;
    const __nv_bfloat16* __restrict__ Bw = which ? g_wprj : g_wkv;
    float* C = which ? outp : g_kv;
    const int N = which ? CDIM : KVW;

    const int tid  = threadIdx.x;
    const int lane = tid & 31;
    const int w    = tid >> 5;
    const int wm   = w >> 2;
    const int wn   = w & 3;
    const int n0   = blockIdx.x * 128;
    const int m0   = blockIdx.y * 128;

    float acc[4][4][4];
#pragma unroll
    for (int mi = 0; mi < 4; mi++)
#pragma unroll
        for (int ni = 0; ni < 4; ni++)
#pragma unroll
            for (int c = 0; c < 4; c++) acc[mi][ni][c] = 0.0f;

    const int srow = tid >> 3;
    const int q    = tid & 7;

    auto issue_stage = [&](int ch, int buf) {
        const uint32_t sa_base = sb + (uint32_t)buf * 32768u;
        const uint32_t sb_base = sa_base + 16384u;
#pragma unroll
        for (int u = 0; u < 4; u++) {
            const int row = srow + 32 * u;
            int am = m0 + row; if (am > MROWS - 1) am = MROWS - 1;
            const uint32_t so = SMEM_SWIZZLE_128B((uint32_t)(row * 128 + q * 16));
            CP_ASYNC16(sa_base + so, A  + (size_t)am * K2 + ch * 64 + q * 8);
            CP_ASYNC16(sb_base + so, Bw + (size_t)(n0 + row) * K2 + ch * 64 + q * 8);
        }
        CP_COMMIT();
    };

    const int NSTAGE = K2 / 64;      // 36
    issue_stage(0, 0);

    for (int ch = 0; ch < NSTAGE; ch++) {
        const int buf = ch & 1;
        if (ch + 1 < NSTAGE) { issue_stage(ch + 1, buf ^ 1); CP_WAIT1(); }
        else                 { CP_WAIT0(); }
        __syncthreads();

        const uint32_t abase = sb + (uint32_t)buf * 32768u;
        const uint32_t bbase = abase + 16384u;
        const int rsel = lane & 15;
        const int chi  = lane >> 4;

#pragma unroll
        for (int kk = 0; kk < 4; kk++) {
            const int c8 = kk * 2 + chi;
            uint32_t af[4][4], bfr[2][4];
#pragma unroll
            for (int mi = 0; mi < 4; mi++) {
                const int row = wm * 64 + mi * 16 + rsel;
                ldsm_x4(af[mi], abase + SMEM_SWIZZLE_128B((uint32_t)(row * 128 + c8 * 16)));
            }
#pragma unroll
            for (int g = 0; g < 2; g++) {
                const int row = wn * 32 + g * 16 + rsel;
                ldsm_x4(bfr[g], bbase + SMEM_SWIZZLE_128B((uint32_t)(row * 128 + c8 * 16)));
            }
#pragma unroll
            for (int mi = 0; mi < 4; mi++)
#pragma unroll
                for (int ni = 0; ni < 4; ni++) {
                    const int g = ni >> 1, o = ni & 1;
                    mma_16816(acc[mi][ni], af[mi], bfr[g][o], bfr[g][o + 2]);
                }
        }
        __syncthreads();
    }

#pragma unroll
    for (int mi = 0; mi < 4; mi++) {
        const int r0 = m0 + wm * 64 + mi * 16 + (lane >> 2);
        const int r1 = r0 + 8;
#pragma unroll
        for (int ni = 0; ni < 4; ni++) {
            const int col = n0 + wn * 32 + ni * 8 + (lane & 3) * 2;
            const float b0v = bias[col], b1v = bias[col + 1];
            if (r0 < MROWS) {
                float2 v = make_float2(acc[mi][ni][0] + b0v, acc[mi][ni][1] + b1v);
                *(float2*)(C + (size_t)r0 * N + col) = v;
            }
            if (r1 < MROWS) {
                float2 v = make_float2(acc[mi][ni][2] + b0v, acc[mi][ni][3] + b1v);
                *(float2*)(C + (size_t)r1 * N + col) = v;
            }
        }
    }
}

// ---------------------------------------------------------------------------
// Tensor-core flash attention, 112.6KB smem => 2 CTAs/SM AND prefetch overlap.
//   KJ double-buffered (2x16KB); VT single-buffered (16KB), loaded during S;
//   KJ(j+1) prefetch issued before the VT wait so it overlaps PV(j).
// Per tile: [wait KJ(j); sync; issue VT(j)] S -> softmax/P ->
//           [issue KJ(j+1); wait VT; sync] PV.
// ---------------------------------------------------------------------------
#define AK_KI_HI 0
#define AK_KI_LO 16384
#define AK_KJ(t) (32768 + (t) * 16384)   // hi +0 (8K), lo +8192 (8K)
#define AK_VT    65536                   // hi +0 (8K), lo +8192 (8K)
#define AK_P_HI  81920
#define AK_P_LO  98304
#define AK_FTAB  114688
#define AK_SMEM  (114688 + 256)

__global__ __launch_bounds__(256, 2) void attn_mma_kernel()
{
    extern __shared__ __align__(128) char sm[];
    const uint32_t sb = smem_u32(sm);
    float* ftab = (float*)(sm + AK_FTAB);

    const int tid = threadIdx.x, lane = tid & 31, w = tid >> 5;
    const int bh = blockIdx.y, b = bh / HEADS, h = bh % HEADS;
    const int i0 = blockIdx.x * 128;

    if (tid < 63) { float xx = (float)tid - 31.0f; ftab[tid] = __expf(-xx * xx * 0.02f); }

    const int srow = tid >> 3, q = tid & 7;

    auto issue_kj = [&](int jt, int t) {
        const uint32_t stg = sb + AK_KJ(t);
#pragma unroll
        for (int u = 0; u < 2; u++) {
            int row = srow + 32 * u;
            const __nv_bfloat16* sk = g_kc + ((size_t)bh * NSEQP + jt + row) * 128 + q * 8;
            uint32_t so = SMEM_SWIZZLE_128B((uint32_t)(row * 128 + q * 16));
            CP_ASYNC16(stg +         so, sk);          // KJ_HI
            CP_ASYNC16(stg + 8192u + so, sk + 64);     // KJ_LO
        }
        CP_COMMIT();
    };
    auto issue_vt = [&](int jt) {
#pragma unroll
        for (int u = 0; u < 2; u++) {
            int row = srow + 32 * u;
            const __nv_bfloat16* sv = g_vt + ((size_t)bh * 64 + row) * (2 * NSEQP) + jt + q * 8;
            uint32_t so = SMEM_SWIZZLE_128B((uint32_t)(row * 128 + q * 16));
            CP_ASYNC16(sb + AK_VT +         so, sv);          // VT_HI
            CP_ASYNC16(sb + AK_VT + 8192u + so, sv + NSEQP);  // VT_LO
        }
        CP_COMMIT();
    };

    // Prologue: Ki (hi/lo) + KJ(0) as one outstanding group-set
    {
#pragma unroll
        for (int u = 0; u < 4; u++) {
            int row = srow + 32 * u;
            int gi = i0 + row; if (gi > NSEQ - 1) gi = NSEQ - 1;
            const __nv_bfloat16* src = g_kc + ((size_t)bh * NSEQP + gi) * 128 + q * 8;
            uint32_t so = SMEM_SWIZZLE_128B((uint32_t)(row * 128 + q * 16));
            CP_ASYNC16(sb + AK_KI_HI + so, src);
            CP_ASYNC16(sb + AK_KI_LO + so, src + 64);
        }
        CP_COMMIT();
        issue_kj(0, 0);
    }

    const int rsel = lane & 15, chi = lane >> 4;
    const int rA = w * 16 + (lane >> 2);
    const int iA = i0 + rA, iB = iA + 8;
    const bool okA = (iA >= 8) && (iA < NSEQ);
    const bool okB = (iB >= 8) && (iB < NSEQ);
    const int qiA1 = (iA - 8) >> 5, qiA2 = (iA - 8) & 31;
    const int qiB1 = (iB - 8) >> 5, qiB2 = (iB - 8) & 31;

    float mA = -1e30f, mB = -1e30f, lA = 0.0f, lB = 0.0f;
    float O[8][4];
#pragma unroll
    for (int ni = 0; ni < 8; ni++)
#pragma unroll
        for (int c = 0; c < 4; c++) O[ni][c] = 0.0f;

    const float scale = 0.125f;

    for (int jt = 0; jt < NSEQP; jt += 64) {
        const int t = (jt >> 6) & 1;
        // Wait KJ(jt) (+ Ki on first iter). Barrier also fences buffer reuse:
        // all warps are past PV(jt-64) (frees VT) and past S(jt-64) in stage t^1.
        CP_WAIT0();
        __syncthreads();
        issue_vt(jt);                       // VT(jt) loads under S + softmax

        const uint32_t stg = sb + AK_KJ(t);

        // ---- S = Ki.Kj^T: passes (hi,hi),(hi,lo),(lo,hi) ----
        float s[8][4];
#pragma unroll
        for (int ni = 0; ni < 8; ni++)
#pragma unroll
            for (int c = 0; c < 4; c++) s[ni][c] = 0.0f;

        const uint32_t apass[3] = {sb + AK_KI_HI, sb + AK_KI_HI, sb + AK_KI_LO};
        const uint32_t bpass[3] = {stg, stg + 8192u, stg};
#pragma unroll
        for (int ps = 0; ps < 3; ps++) {
#pragma unroll
            for (int kk = 0; kk < 4; kk++) {
                const int c8 = kk * 2 + chi;
                uint32_t af[4], bfr[4][4];
                ldsm_x4(af, apass[ps] +
                        SMEM_SWIZZLE_128B((uint32_t)((w * 16 + rsel) * 128 + c8 * 16)));
#pragma unroll
                for (int g = 0; g < 4; g++)
                    ldsm_x4(bfr[g], bpass[ps] +
                            SMEM_SWIZZLE_128B((uint32_t)((g * 16 + rsel) * 128 + c8 * 16)));
#pragma unroll
                for (int ni = 0; ni < 8; ni++)
                    mma_16816(s[ni], af, bfr[ni >> 1][ni & 1], bfr[ni >> 1][(ni & 1) + 2]);
            }
        }

        // ---- scale + gaussian bias + tail mask ----
#pragma unroll
        for (int ni = 0; ni < 8; ni++) {
            const int jbase = jt + ni * 8 + ((lane & 3) << 1);
#pragma unroll
            for (int c = 0; c < 4; c++) {
                const int j = jbase + (c & 1);
                float val = s[ni][c] * scale;
                const bool ok = (c < 2) ? okA : okB;
                const int q1 = (c < 2) ? qiA1 : qiB1;
                const int q2 = (c < 2) ? qiA2 : qiB2;
                if (j < NSEQ) {
                    if (ok && j >= 8)
                        val += ftab[q1 - ((j - 8) >> 5) + 31] * ftab[q2 - ((j - 8) & 31) + 31];
                } else val = -1e30f;
                s[ni][c] = val;
            }
        }

        // ---- online softmax ----
        float tA = -1e30f, tB = -1e30f;
#pragma unroll
        for (int ni = 0; ni < 8; ni++) {
            tA = fmaxf(tA, fmaxf(s[ni][0], s[ni][1]));
            tB = fmaxf(tB, fmaxf(s[ni][2], s[ni][3]));
        }
        tA = fmaxf(tA, __shfl_xor_sync(0xffffffffu, tA, 1));
        tA = fmaxf(tA, __shfl_xor_sync(0xffffffffu, tA, 2));
        tB = fmaxf(tB, __shfl_xor_sync(0xffffffffu, tB, 1));
        tB = fmaxf(tB, __shfl_xor_sync(0xffffffffu, tB, 2));
        const float mnA = fmaxf(mA, tA), mnB = fmaxf(mB, tB);
        const float cA = __expf(mA - mnA), cB = __expf(mB - mnB);
        float rsA = 0.0f, rsB = 0.0f;
#pragma unroll
        for (int ni = 0; ni < 8; ni++) {
            s[ni][0] = __expf(s[ni][0] - mnA); rsA += s[ni][0];
            s[ni][1] = __expf(s[ni][1] - mnA); rsA += s[ni][1];
            s[ni][2] = __expf(s[ni][2] - mnB); rsB += s[ni][2];
            s[ni][3] = __expf(s[ni][3] - mnB); rsB += s[ni][3];
        }
        rsA += __shfl_xor_sync(0xffffffffu, rsA, 1);
        rsA += __shfl_xor_sync(0xffffffffu, rsA, 2);
        rsB += __shfl_xor_sync(0xffffffffu, rsB, 1);
        rsB += __shfl_xor_sync(0xffffffffu, rsB, 2);
        lA = lA * cA + rsA; lB = lB * cB + rsB;
        mA = mnA; mB = mnB;

        // ---- P -> smem (hi/lo, warp-private rows) + O rescale ----
        const uint32_t rowoffA = (uint32_t)((w * 16 + (lane >> 2)) * 128 + (lane & 3) * 4);
        const uint32_t rowoffB = rowoffA + 8 * 128;
#pragma unroll
        for (int ni = 0; ni < 8; ni++) {
            O[ni][0] *= cA; O[ni][1] *= cA; O[ni][2] *= cB; O[ni][3] *= cB;

            __nv_bfloat16 h0 = __float2bfloat16(s[ni][0]);
            __nv_bfloat16 h1 = __float2bfloat16(s[ni][1]);
            __nv_bfloat162 hv; hv.x = h0; hv.y = h1;
            __nv_bfloat162 lv;
            lv.x = __float2bfloat16(s[ni][0] - __bfloat162float(h0));
            lv.y = __float2bfloat16(s[ni][1] - __bfloat162float(h1));
            const uint32_t offA = SMEM_SWIZZLE_128B(rowoffA + ni * 16);
            *(__nv_bfloat162*)(sm + AK_P_HI + offA) = hv;
            *(__nv_bfloat162*)(sm + AK_P_LO + offA) = lv;

            __nv_bfloat16 h2 = __float2bfloat16(s[ni][2]);
            __nv_bfloat16 h3 = __float2bfloat16(s[ni][3]);
            __nv_bfloat162 hv2; hv2.x = h2; hv2.y = h3;
            __nv_bfloat162 lv2;
            lv2.x = __float2bfloat16(s[ni][2] - __bfloat162float(h2));
            lv2.y = __float2bfloat16(s[ni][3] - __bfloat162float(h3));
            const uint32_t offB = SMEM_SWIZZLE_128B(rowoffB + ni * 16);
            *(__nv_bfloat162*)(sm + AK_P_HI + offB) = hv2;
            *(__nv_bfloat162*)(sm + AK_P_LO + offB) = lv2;
        }

        // Prefetch KJ(jt+64) (overlaps PV), then ensure VT(jt) is resident.
        if (jt + 64 < NSEQP) { issue_kj(jt + 64, t ^ 1); CP_WAIT1(); }
        else                 { CP_WAIT0(); }
        __syncthreads();   // VT visible to all warps; P warp-private (no cross-warp read)

        // ---- O += P.V: passes (P_hi,V_hi),(P_hi,V_lo),(P_lo,V_hi) ----
        const uint32_t papass[3] = {sb + AK_P_HI, sb + AK_P_HI, sb + AK_P_LO};
        const uint32_t vbpass[3] = {sb + AK_VT, sb + AK_VT + 8192u, sb + AK_VT};
#pragma unroll
        for (int ps = 0; ps < 3; ps++) {
#pragma unroll
            for (int kk = 0; kk < 4; kk++) {
                const int c8 = kk * 2 + chi;
                uint32_t af[4], bfr[4][4];
                ldsm_x4(af, papass[ps] +
                        SMEM_SWIZZLE_128B((uint32_t)((w * 16 + rsel) * 128 + c8 * 16)));
#pragma unroll
                for (int g = 0; g < 4; g++)
                    ldsm_x4(bfr[g], vbpass[ps] +
                            SMEM_SWIZZLE_128B((uint32_t)((g * 16 + rsel) * 128 + c8 * 16)));
#pragma unroll
                for (int ni = 0; ni < 8; ni++)
                    mma_16816(O[ni], af, bfr[ni >> 1][ni & 1], bfr[ni >> 1][(ni & 1) + 2]);
            }
        }
    }

    // ---- epilogue: normalize, write triple-block g_attc directly ----
    const float invA = 1.0f / lA, invB = 1.0f / lB;
#pragma unroll
    for (int ni = 0; ni < 8; ni++) {
        const int d = ni * 8 + ((lane & 3) << 1);
        if (iA < NSEQ) {
            float v0 = O[ni][0] * invA, v1 = O[ni][1] * invA;
            __nv_bfloat162 hv, lv;
            hv.x = __float2bfloat16(v0); hv.y = __float2bfloat16(v1);
            lv.x = __float2bfloat16(v0 - __bfloat162float(hv.x));
            lv.y = __float2bfloat16(v1 - __bfloat162float(hv.y));
            __nv_bfloat16* dst = g_attc + (size_t)(b * NSEQ + iA) * K2 + h * HD + d;
            *(__nv_bfloat162*)(dst)            = hv;
            *(__nv_bfloat162*)(dst + CDIM)     = hv;
            *(__nv_bfloat162*)(dst + 2 * CDIM) = lv;
        }
        if (iB < NSEQ) {
            float v0 = O[ni][2] * invB, v1 = O[ni][3] * invB;
            __nv_bfloat162 hv, lv;
            hv.x = __float2bfloat16(v0); hv.y = __float2bfloat16(v1);
            lv.x = __float2bfloat16(v0 - __bfloat162float(hv.x));
            lv.y = __float2bfloat16(v1 - __bfloat162float(hv.y));
            __nv_bfloat16* dst = g_attc + (size_t)(b * NSEQ + iB) * K2 + h * HD + d;
            *(__nv_bfloat162*)(dst)            = hv;
            *(__nv_bfloat162*)(dst + CDIM)     = hv;
            *(__nv_bfloat162*)(dst + 2 * CDIM) = lv;
        }
    }
}

// ---------------------------------------------------------------------------
extern "C" void kernel_launch(void* const* d_in, const int* in_sizes, int n_in,
                              void* d_out, int out_size)
{
    const float* x = nullptr;
    const float* qkv_w = nullptr;
    const float* qkv_b = nullptr;
    const float* proj_w = nullptr;
    const float* proj_b = nullptr;
    for (int i = 0; i < n_in; i++) {
        switch (in_sizes[i]) {
            case 6340608: x      = (const float*)d_in[i]; break;
            case 1769472: qkv_w  = (const float*)d_in[i]; break;
            case 2304:    qkv_b  = (const float*)d_in[i]; break;
            case 589824:  proj_w = (const float*)d_in[i]; break;
            case 768:     proj_b = (const float*)d_in[i]; break;
        }
    }
    float* out = (float*)d_out;

    cudaFuncSetAttribute(gemm_mma_kernel, cudaFuncAttributeMaxDynamicSharedMemorySize, GEMM_SMEM);
    cudaFuncSetAttribute(attn_mma_kernel, cudaFuncAttributeMaxDynamicSharedMemorySize, AK_SMEM);

    // conversions: x, W_kv, W_proj -> triple-block bf16
    {
        size_t t4 = (size_t)MROWS * CDIM / 4;
        conv_dual_kernel<<<(unsigned)((t4 + 255) / 256), 256>>>(x, 0, MROWS, CDIM, 0);
        t4 = (size_t)KVW * CDIM / 4;
        conv_dual_kernel<<<(unsigned)((t4 + 255) / 256), 256>>>(qkv_w, 2, KVW, CDIM, CDIM);
        t4 = (size_t)CDIM * CDIM / 4;
        conv_dual_kernel<<<(unsigned)((t4 + 255) / 256), 256>>>(proj_w, 3, CDIM, CDIM, 0);
    }
    // 1) K,V projection via HMMA -> g_kv (fp32)
    {
        dim3 grid(KVW / 128, (MROWS + 127) / 128);   // 12 x 65
        gemm_mma_kernel<<<grid, 256, GEMM_SMEM>>>(0, qkv_b + CDIM, nullptr);
    }
    // 2) K/V panel conversion (hi/lo bf16, V transposed)
    {
        dim3 grid(17, NPANEL);                       // 17 x 96
        conv_kv_kernel<<<grid, 256>>>();
    }
    // 3) tensor-core flash attention -> g_attc (triple-block, direct)
    {
        dim3 grid((NSEQ + 127) / 128, NPANEL);       // 9 x 96
        attn_mma_kernel<<<grid, 256, AK_SMEM>>>();
    }
    // 4) output projection via HMMA -> d_out
    {
        dim3 grid(CDIM / 128, (MROWS + 127) / 128);  // 6 x 65
        gemm_mma_kernel<<<grid, 256, GEMM_SMEM>>>(1, proj_b, out);
    }
}

// round 13
// speedup vs baseline: 1.1310x; 1.0771x over previous
#include <cuda_runtime.h>
#include <cuda_bf16.h>
#include <cstdint>
#include <cstddef>

// Problem constants
#define BATCH 8
#define NSEQ  1032          // 32*32 + 8
#define NSEQP 1088          // padded to 17*64
#define CDIM  768
#define HEADS 12
#define HD    64
#define MROWS (BATCH*NSEQ)  // 8256
#define KVW   1536          // k+v columns
#define K2    2304          // triple-block K (3*768): A=[hi|hi|lo], B=[hi|lo|hi]
#define NPANEL (BATCH*HEADS) // 96

// Device scratch (static globals — zero-initialized, no runtime allocation).
__device__ float g_kv[(size_t)MROWS * KVW];          // K|V fp32
__device__ float g_att[(size_t)MROWS * CDIM];        // attention output fp32
__device__ __nv_bfloat16 g_xc  [(size_t)MROWS * K2]; // x       A-type [hi|hi|lo]
__device__ __nv_bfloat16 g_attc[(size_t)MROWS * K2]; // attnout A-type [hi|hi|lo]
__device__ __nv_bfloat16 g_wkv [(size_t)KVW   * K2]; // qkv_w rows 768.. B-type [hi|lo|hi]
__device__ __nv_bfloat16 g_wprj[(size_t)CDIM  * K2]; // proj_w B-type [hi|lo|hi]
__device__ __nv_bfloat16 g_kc[(size_t)NPANEL * NSEQP * 128];    // per (b,h): [j][K_hi(64)|K_lo(64)]
__device__ __nv_bfloat16 g_vt[(size_t)NPANEL * 64 * 2 * NSEQP]; // per (b,h): [d][Vt_hi(NSEQP)|Vt_lo(NSEQP)]

// ---------------------------------------------------------------------------
// Helpers (portable PTX: ldmatrix / mma.sync / cp.async)
// ---------------------------------------------------------------------------
__device__ __forceinline__ uint32_t smem_u32(const void* p) {
    uint32_t a;
    asm("{ .reg .u64 t; cvta.to.shared.u64 t, %1; cvt.u32.u64 %0, t; }" : "=r"(a) : "l"(p));
    return a;
}
#define SMEM_SWIZZLE_128B(x) ((x) ^ (((x) >> 3) & 0x70))

#define CP_ASYNC16(sa, ga) \
    asm volatile("cp.async.cg.shared.global [%0], [%1], 16;" :: "r"(sa), "l"(ga) : "memory")
#define CP_COMMIT() asm volatile("cp.async.commit_group;" ::: "memory")
#define CP_WAIT1()  asm volatile("cp.async.wait_group 1;" ::: "memory")
#define CP_WAIT0()  asm volatile("cp.async.wait_group 0;" ::: "memory")

__device__ __forceinline__ void ldsm_x4(uint32_t* r, uint32_t addr) {
    asm volatile("ldmatrix.sync.aligned.m8n8.x4.shared.b16 {%0,%1,%2,%3}, [%4];"
                 : "=r"(r[0]), "=r"(r[1]), "=r"(r[2]), "=r"(r[3]) : "r"(addr));
}

__device__ __forceinline__ void mma_16816(float* c, const uint32_t* a,
                                          uint32_t b0, uint32_t b1) {
    asm volatile("mma.sync.aligned.m16n8k16.row.col.f32.bf16.bf16.f32 "
                 "{%0,%1,%2,%3}, {%4,%5,%6,%7}, {%8,%9}, {%0,%1,%2,%3};"
                 : "+f"(c[0]), "+f"(c[1]), "+f"(c[2]), "+f"(c[3])
                 : "r"(a[0]), "r"(a[1]), "r"(a[2]), "r"(a[3]), "r"(b0), "r"(b1));
}

// ---------------------------------------------------------------------------
// Triple-block conversion.
//   A-type (which 0,1): dst = [hi | hi | lo]
//   B-type (which 2,3): dst = [hi | lo | hi]
// which: 0=g_xc(from x) 1=g_attc(from g_att) 2=g_wkv(qkv_w rows 768..) 3=g_wprj(proj_w)
// ---------------------------------------------------------------------------
__global__ __launch_bounds__(256) void conv_dual_kernel(
    const float* __restrict__ src_ext, int which, int R, int K, int srow_off)
{
    __nv_bfloat16* dst = (which == 0) ? g_xc : (which == 1) ? g_attc
                       : (which == 2) ? g_wkv : g_wprj;
    const float* src = (which == 1) ? g_att : src_ext;
    const bool atype = (which <= 1);

    size_t total4 = (size_t)R * K / 4;
    size_t idx = (size_t)blockIdx.x * blockDim.x + threadIdx.x;
    if (idx >= total4) return;
    int kq = (int)(idx % (K / 4));
    int r  = (int)(idx / (K / 4));
    float4 v = *(const float4*)(src + (size_t)(srow_off + r) * K + kq * 4);
    __nv_bfloat16 h0 = __float2bfloat16(v.x);
    __nv_bfloat16 h1 = __float2bfloat16(v.y);
    __nv_bfloat16 h2 = __float2bfloat16(v.z);
    __nv_bfloat16 h3 = __float2bfloat16(v.w);
    __nv_bfloat16 l0 = __float2bfloat16(v.x - __bfloat162float(h0));
    __nv_bfloat16 l1 = __float2bfloat16(v.y - __bfloat162float(h1));
    __nv_bfloat16 l2 = __float2bfloat16(v.z - __bfloat162float(h2));
    __nv_bfloat16 l3 = __float2bfloat16(v.w - __bfloat162float(h3));

    __nv_bfloat16* d0 = dst + (size_t)r * K2 + kq * 4;
    __nv_bfloat16* d1 = d0 + K;
    __nv_bfloat16* d2 = d0 + 2 * K;
    d0[0] = h0; d0[1] = h1; d0[2] = h2; d0[3] = h3;
    if (atype) {
        d1[0] = h0; d1[1] = h1; d1[2] = h2; d1[3] = h3;
        d2[0] = l0; d2[1] = l1; d2[2] = l2; d2[3] = l3;
    } else {
        d1[0] = l0; d1[1] = l1; d1[2] = l2; d1[3] = l3;
        d2[0] = h0; d2[1] = h1; d2[2] = h2; d2[3] = h3;
    }
}

// ---------------------------------------------------------------------------
// K/V panel conversion: g_kv fp32 -> g_kc (K hi|lo) + g_vt (V^T hi|lo)
// ---------------------------------------------------------------------------
__global__ __launch_bounds__(256) void conv_kv_kernel()
{
    __shared__ float vt[64][65];
    const int tid = threadIdx.x;
    const int bh = blockIdx.y, b = bh / HEADS, h = bh % HEADS;
    const int j0 = blockIdx.x * 64;

#pragma unroll
    for (int it = 0; it < 16; it++) {
        int idx = tid + 256 * it;
        int j = idx >> 6, d = idx & 63;
        int gj = j0 + j;
        float vvv = 0.0f;
        if (gj < NSEQ) {
            const float* src = g_kv + ((size_t)b * NSEQ + gj) * KVW + h * HD;
            float kvv = src[d];
            vvv = src[CDIM + d];
            __nv_bfloat16 hi = __float2bfloat16(kvv);
            __nv_bfloat16 lo = __float2bfloat16(kvv - __bfloat162float(hi));
            __nv_bfloat16* dst = g_kc + ((size_t)bh * NSEQP + gj) * 128;
            dst[d] = hi; dst[64 + d] = lo;
        }
        vt[j][d] = vvv;
    }
    __syncthreads();
#pragma unroll
    for (int it = 0; it < 16; it++) {
        int idx = tid + 256 * it;
        int d = idx >> 6, j = idx & 63;
        int gj = j0 + j;
        if (gj < NSEQ) {
            float v = vt[j][d];
            __nv_bfloat16 hi = __float2bfloat16(v);
            __nv_bfloat16 lo = __float2bfloat16(v - __bfloat162float(hi));
            __nv_bfloat16* dst = g_vt + ((size_t)bh * 64 + d) * (2 * NSEQP);
            dst[gj] = hi; dst[NSEQP + gj] = lo;
        }
    }
}

// ---------------------------------------------------------------------------
// HMMA GEMM over K2=2304. launch_bounds(256,2): verified 206 -> 175 us.
// ---------------------------------------------------------------------------
#define GEMM_SMEM 65536

__global__ __launch_bounds__(256, 2) void gemm_mma_kernel(
    int which, const float* __restrict__ bias, float* __restrict__ outp)
{
    extern __shared__ __align__(128) char smem[];
    const uint32_t sb = smem_u32(smem);

    const __nv_bfloat16* __restrict__ A  = which ? g_attc : g_xc;
    const __nv_bfloat16* __restrict__ Bw = which ? g_wprj : g_wkv;
    float* C = which ? outp : g_kv;
    const int N = which ? CDIM : KVW;

    const int tid  = threadIdx.x;
    const int lane = tid & 31;
    const int w    = tid >> 5;
    const int wm   = w >> 2;
    const int wn   = w & 3;
    const int n0   = blockIdx.x * 128;
    const int m0   = blockIdx.y * 128;

    float acc[4][4][4];
#pragma unroll
    for (int mi = 0; mi < 4; mi++)
#pragma unroll
        for (int ni = 0; ni < 4; ni++)
#pragma unroll
            for (int c = 0; c < 4; c++) acc[mi][ni][c] = 0.0f;

    const int srow = tid >> 3;
    const int q    = tid & 7;

    auto issue_stage = [&](int ch, int buf) {
        const uint32_t sa_base = sb + (uint32_t)buf * 32768u;
        const uint32_t sb_base = sa_base + 16384u;
#pragma unroll
        for (int u = 0; u < 4; u++) {
            const int row = srow + 32 * u;
            int am = m0 + row; if (am > MROWS - 1) am = MROWS - 1;
            const uint32_t so = SMEM_SWIZZLE_128B((uint32_t)(row * 128 + q * 16));
            CP_ASYNC16(sa_base + so, A  + (size_t)am * K2 + ch * 64 + q * 8);
            CP_ASYNC16(sb_base + so, Bw + (size_t)(n0 + row) * K2 + ch * 64 + q * 8);
        }
        CP_COMMIT();
    };

    const int NSTAGE = K2 / 64;      // 36
    issue_stage(0, 0);

    for (int ch = 0; ch < NSTAGE; ch++) {
        const int buf = ch & 1;
        if (ch + 1 < NSTAGE) { issue_stage(ch + 1, buf ^ 1); CP_WAIT1(); }
        else                 { CP_WAIT0(); }
        __syncthreads();

        const uint32_t abase = sb + (uint32_t)buf * 32768u;
        const uint32_t bbase = abase + 16384u;
        const int rsel = lane & 15;
        const int chi  = lane >> 4;

#pragma unroll
        for (int kk = 0; kk < 4; kk++) {
            const int c8 = kk * 2 + chi;
            uint32_t af[4][4], bfr[2][4];
#pragma unroll
            for (int mi = 0; mi < 4; mi++) {
                const int row = wm * 64 + mi * 16 + rsel;
                ldsm_x4(af[mi], abase + SMEM_SWIZZLE_128B((uint32_t)(row * 128 + c8 * 16)));
            }
#pragma unroll
            for (int g = 0; g < 2; g++) {
                const int row = wn * 32 + g * 16 + rsel;
                ldsm_x4(bfr[g], bbase + SMEM_SWIZZLE_128B((uint32_t)(row * 128 + c8 * 16)));
            }
#pragma unroll
            for (int mi = 0; mi < 4; mi++)
#pragma unroll
                for (int ni = 0; ni < 4; ni++) {
                    const int g = ni >> 1, o = ni & 1;
                    mma_16816(acc[mi][ni], af[mi], bfr[g][o], bfr[g][o + 2]);
                }
        }
        __syncthreads();
    }

#pragma unroll
    for (int mi = 0; mi < 4; mi++) {
        const int r0 = m0 + wm * 64 + mi * 16 + (lane >> 2);
        const int r1 = r0 + 8;
#pragma unroll
        for (int ni = 0; ni < 4; ni++) {
            const int col = n0 + wn * 32 + ni * 8 + (lane & 3) * 2;
            const float b0v = bias[col], b1v = bias[col + 1];
            if (r0 < MROWS) {
                float2 v = make_float2(acc[mi][ni][0] + b0v, acc[mi][ni][1] + b1v);
                *(float2*)(C + (size_t)r0 * N + col) = v;
            }
            if (r1 < MROWS) {
                float2 v = make_float2(acc[mi][ni][2] + b0v, acc[mi][ni][3] + b1v);
                *(float2*)(C + (size_t)r1 * N + col) = v;
            }
        }
    }
}

// ---------------------------------------------------------------------------
// Tensor-core flash attention — EXACT 778us configuration:
// 98.5KB smem, no min-blocks cap, single-buffered j-tiles, fp32 g_att epilogue.
// ---------------------------------------------------------------------------
#define AK_KI_HI 0
#define AK_KI_LO 16384
#define AK_KJ_HI 32768
#define AK_KJ_LO 40960
#define AK_VT_HI 49152
#define AK_VT_LO 57344
#define AK_P_HI  65536
#define AK_P_LO  81920
#define AK_FTAB  98304
#define AK_SMEM  (98304 + 256)

__global__ __launch_bounds__(256) void attn_mma_kernel()
{
    extern __shared__ __align__(128) char sm[];
    const uint32_t sb = smem_u32(sm);
    float* ftab = (float*)(sm + AK_FTAB);

    const int tid = threadIdx.x, lane = tid & 31, w = tid >> 5;
    const int bh = blockIdx.y, b = bh / HEADS, h = bh % HEADS;
    const int i0 = blockIdx.x * 128;

    if (tid < 63) { float xx = (float)tid - 31.0f; ftab[tid] = __expf(-xx * xx * 0.02f); }

    // Ki tiles (hi/lo), loaded once
    {
        const int srow = tid >> 3, q = tid & 7;
#pragma unroll
        for (int u = 0; u < 4; u++) {
            int row = srow + 32 * u;
            int gi = i0 + row; if (gi > NSEQ - 1) gi = NSEQ - 1;
            const __nv_bfloat16* src = g_kc + ((size_t)bh * NSEQP + gi) * 128 + q * 8;
            uint32_t so = SMEM_SWIZZLE_128B((uint32_t)(row * 128 + q * 16));
            CP_ASYNC16(sb + AK_KI_HI + so, src);
            CP_ASYNC16(sb + AK_KI_LO + so, src + 64);
        }
        CP_COMMIT();
    }

    const int rsel = lane & 15, chi = lane >> 4;
    const int rA = w * 16 + (lane >> 2);
    const int iA = i0 + rA, iB = iA + 8;
    const bool okA = (iA >= 8) && (iA < NSEQ);
    const bool okB = (iB >= 8) && (iB < NSEQ);
    const int qiA1 = (iA - 8) >> 5, qiA2 = (iA - 8) & 31;
    const int qiB1 = (iB - 8) >> 5, qiB2 = (iB - 8) & 31;

    float mA = -1e30f, mB = -1e30f, lA = 0.0f, lB = 0.0f;
    float O[8][4];
#pragma unroll
    for (int ni = 0; ni < 8; ni++)
#pragma unroll
        for (int c = 0; c < 4; c++) O[ni][c] = 0.0f;

    const float scale = 0.125f;

    for (int jt = 0; jt < NSEQP; jt += 64) {
        __syncthreads();   // prior tile fully consumed by all warps
        {
            const int srow = tid >> 3, q = tid & 7;
#pragma unroll
            for (int u = 0; u < 2; u++) {
                int row = srow + 32 * u;
                const __nv_bfloat16* sk = g_kc + ((size_t)bh * NSEQP + jt + row) * 128 + q * 8;
                const __nv_bfloat16* sv = g_vt + ((size_t)bh * 64 + row) * (2 * NSEQP) + jt + q * 8;
                uint32_t so = SMEM_SWIZZLE_128B((uint32_t)(row * 128 + q * 16));
                CP_ASYNC16(sb + AK_KJ_HI + so, sk);
                CP_ASYNC16(sb + AK_KJ_LO + so, sk + 64);
                CP_ASYNC16(sb + AK_VT_HI + so, sv);
                CP_ASYNC16(sb + AK_VT_LO + so, sv + NSEQP);
            }
            CP_COMMIT(); CP_WAIT0();
        }
        __syncthreads();

        // ---- S = Ki.Kj^T: passes (hi,hi),(hi,lo),(lo,hi) ----
        float s[8][4];
#pragma unroll
        for (int ni = 0; ni < 8; ni++)
#pragma unroll
            for (int c = 0; c < 4; c++) s[ni][c] = 0.0f;

        const uint32_t apass[3] = {AK_KI_HI, AK_KI_LO + 0u, AK_KI_LO};
        // NOTE: pass order (hi,hi),(hi,lo),(lo,hi) — apass fixed below
        const uint32_t apass2[3] = {AK_KI_HI, AK_KI_HI, AK_KI_LO};
        const uint32_t bpass[3] = {AK_KJ_HI, AK_KJ_LO, AK_KJ_HI};
#pragma unroll
        for (int ps = 0; ps < 3; ps++) {
#pragma unroll
            for (int kk = 0; kk < 4; kk++) {
                const int c8 = kk * 2 + chi;
                uint32_t af[4], bfr[4][4];
                ldsm_x4(af, sb + apass2[ps] +
                        SMEM_SWIZZLE_128B((uint32_t)((w * 16 + rsel) * 128 + c8 * 16)));
#pragma unroll
                for (int g = 0; g < 4; g++)
                    ldsm_x4(bfr[g], sb + bpass[ps] +
                            SMEM_SWIZZLE_128B((uint32_t)((g * 16 + rsel) * 128 + c8 * 16)));
#pragma unroll
                for (int ni = 0; ni < 8; ni++)
                    mma_16816(s[ni], af, bfr[ni >> 1][ni & 1], bfr[ni >> 1][(ni & 1) + 2]);
            }
        }
        (void)apass;

        // ---- scale + gaussian bias + tail mask ----
#pragma unroll
        for (int ni = 0; ni < 8; ni++) {
            const int jbase = jt + ni * 8 + ((lane & 3) << 1);
#pragma unroll
            for (int c = 0; c < 4; c++) {
                const int j = jbase + (c & 1);
                float val = s[ni][c] * scale;
                const bool ok = (c < 2) ? okA : okB;
                const int q1 = (c < 2) ? qiA1 : qiB1;
                const int q2 = (c < 2) ? qiA2 : qiB2;
                if (j < NSEQ) {
                    if (ok && j >= 8)
                        val += ftab[q1 - ((j - 8) >> 5) + 31] * ftab[q2 - ((j - 8) & 31) + 31];
                } else val = -1e30f;
                s[ni][c] = val;
            }
        }

        // ---- online softmax ----
        float tA = -1e30f, tB = -1e30f;
#pragma unroll
        for (int ni = 0; ni < 8; ni++) {
            tA = fmaxf(tA, fmaxf(s[ni][0], s[ni][1]));
            tB = fmaxf(tB, fmaxf(s[ni][2], s[ni][3]));
        }
        tA = fmaxf(tA, __shfl_xor_sync(0xffffffffu, tA, 1));
        tA = fmaxf(tA, __shfl_xor_sync(0xffffffffu, tA, 2));
        tB = fmaxf(tB, __shfl_xor_sync(0xffffffffu, tB, 1));
        tB = fmaxf(tB, __shfl_xor_sync(0xffffffffu, tB, 2));
        const float mnA = fmaxf(mA, tA), mnB = fmaxf(mB, tB);
        const float cA = __expf(mA - mnA), cB = __expf(mB - mnB);
        float rsA = 0.0f, rsB = 0.0f;
#pragma unroll
        for (int ni = 0; ni < 8; ni++) {
            s[ni][0] = __expf(s[ni][0] - mnA); rsA += s[ni][0];
            s[ni][1] = __expf(s[ni][1] - mnA); rsA += s[ni][1];
            s[ni][2] = __expf(s[ni][2] - mnB); rsB += s[ni][2];
            s[ni][3] = __expf(s[ni][3] - mnB); rsB += s[ni][3];
        }
        rsA += __shfl_xor_sync(0xffffffffu, rsA, 1);
        rsA += __shfl_xor_sync(0xffffffffu, rsA, 2);
        rsB += __shfl_xor_sync(0xffffffffu, rsB, 1);
        rsB += __shfl_xor_sync(0xffffffffu, rsB, 2);
        lA = lA * cA + rsA; lB = lB * cB + rsB;
        mA = mnA; mB = mnB;

        // ---- P -> smem (hi/lo, warp-private rows) + O rescale ----
        const uint32_t rowoffA = (uint32_t)((w * 16 + (lane >> 2)) * 128 + (lane & 3) * 4);
        const uint32_t rowoffB = rowoffA + 8 * 128;
#pragma unroll
        for (int ni = 0; ni < 8; ni++) {
            O[ni][0] *= cA; O[ni][1] *= cA; O[ni][2] *= cB; O[ni][3] *= cB;

            __nv_bfloat16 h0 = __float2bfloat16(s[ni][0]);
            __nv_bfloat16 h1 = __float2bfloat16(s[ni][1]);
            __nv_bfloat162 hv; hv.x = h0; hv.y = h1;
            __nv_bfloat162 lv;
            lv.x = __float2bfloat16(s[ni][0] - __bfloat162float(h0));
            lv.y = __float2bfloat16(s[ni][1] - __bfloat162float(h1));
            const uint32_t offA = SMEM_SWIZZLE_128B(rowoffA + ni * 16);
            *(__nv_bfloat162*)(sm + AK_P_HI + offA) = hv;
            *(__nv_bfloat162*)(sm + AK_P_LO + offA) = lv;

            __nv_bfloat16 h2 = __float2bfloat16(s[ni][2]);
            __nv_bfloat16 h3 = __float2bfloat16(s[ni][3]);
            __nv_bfloat162 hv2; hv2.x = h2; hv2.y = h3;
            __nv_bfloat162 lv2;
            lv2.x = __float2bfloat16(s[ni][2] - __bfloat162float(h2));
            lv2.y = __float2bfloat16(s[ni][3] - __bfloat162float(h3));
            const uint32_t offB = SMEM_SWIZZLE_128B(rowoffB + ni * 16);
            *(__nv_bfloat162*)(sm + AK_P_HI + offB) = hv2;
            *(__nv_bfloat162*)(sm + AK_P_LO + offB) = lv2;
        }
        __syncwarp();

        // ---- O += P.V: passes (P_hi,V_hi),(P_hi,V_lo),(P_lo,V_hi) ----
        const uint32_t papass[3] = {AK_P_HI, AK_P_HI, AK_P_LO};
        const uint32_t vbpass[3] = {AK_VT_HI, AK_VT_LO, AK_VT_HI};
#pragma unroll
        for (int ps = 0; ps < 3; ps++) {
#pragma unroll
            for (int kk = 0; kk < 4; kk++) {
                const int c8 = kk * 2 + chi;
                uint32_t af[4], bfr[4][4];
                ldsm_x4(af, sb + papass[ps] +
                        SMEM_SWIZZLE_128B((uint32_t)((w * 16 + rsel) * 128 + c8 * 16)));
#pragma unroll
                for (int g = 0; g < 4; g++)
                    ldsm_x4(bfr[g], sb + vbpass[ps] +
                            SMEM_SWIZZLE_128B((uint32_t)((g * 16 + rsel) * 128 + c8 * 16)));
#pragma unroll
                for (int ni = 0; ni < 8; ni++)
                    mma_16816(O[ni], af, bfr[ni >> 1][ni & 1], bfr[ni >> 1][(ni & 1) + 2]);
            }
        }
    }

    // ---- epilogue: normalize, write fp32 g_att (coalesced float2) ----
    const float invA = 1.0f / lA, invB = 1.0f / lB;
#pragma unroll
    for (int ni = 0; ni < 8; ni++) {
        const int d = ni * 8 + ((lane & 3) << 1);
        if (iA < NSEQ) {
            float2 v = make_float2(O[ni][0] * invA, O[ni][1] * invA);
            *(float2*)(g_att + ((size_t)(b * NSEQ + iA)) * CDIM + h * HD + d) = v;
        }
        if (iB < NSEQ) {
            float2 v = make_float2(O[ni][2] * invB, O[ni][3] * invB);
            *(float2*)(g_att + ((size_t)(b * NSEQ + iB)) * CDIM + h * HD + d) = v;
        }
    }
}

// ---------------------------------------------------------------------------
extern "C" void kernel_launch(void* const* d_in, const int* in_sizes, int n_in,
                              void* d_out, int out_size)
{
    const float* x = nullptr;
    const float* qkv_w = nullptr;
    const float* qkv_b = nullptr;
    const float* proj_w = nullptr;
    const float* proj_b = nullptr;
    for (int i = 0; i < n_in; i++) {
        switch (in_sizes[i]) {
            case 6340608: x      = (const float*)d_in[i]; break;
            case 1769472: qkv_w  = (const float*)d_in[i]; break;
            case 2304:    qkv_b  = (const float*)d_in[i]; break;
            case 589824:  proj_w = (const float*)d_in[i]; break;
            case 768:     proj_b = (const float*)d_in[i]; break;
        }
    }
    float* out = (float*)d_out;

    cudaFuncSetAttribute(gemm_mma_kernel, cudaFuncAttributeMaxDynamicSharedMemorySize, GEMM_SMEM);
    cudaFuncSetAttribute(attn_mma_kernel, cudaFuncAttributeMaxDynamicSharedMemorySize, AK_SMEM);

    // conversions: x, W_kv, W_proj -> triple-block bf16
    {
        size_t t4 = (size_t)MROWS * CDIM / 4;
        conv_dual_kernel<<<(unsigned)((t4 + 255) / 256), 256>>>(x, 0, MROWS, CDIM, 0);
        t4 = (size_t)KVW * CDIM / 4;
        conv_dual_kernel<<<(unsigned)((t4 + 255) / 256), 256>>>(qkv_w, 2, KVW, CDIM, CDIM);
        t4 = (size_t)CDIM * CDIM / 4;
        conv_dual_kernel<<<(unsigned)((t4 + 255) / 256), 256>>>(proj_w, 3, CDIM, CDIM, 0);
    }
    // 1) K,V projection via HMMA -> g_kv (fp32)
    {
        dim3 grid(KVW / 128, (MROWS + 127) / 128);   // 12 x 65
        gemm_mma_kernel<<<grid, 256, GEMM_SMEM>>>(0, qkv_b + CDIM, nullptr);
    }
    // 2) K/V panel conversion (hi/lo bf16, V transposed)
    {
        dim3 grid(17, NPANEL);                       // 17 x 96
        conv_kv_kernel<<<grid, 256>>>();
    }
    // 3) tensor-core flash attention -> g_att (fp32)
    {
        dim3 grid((NSEQ + 127) / 128, NPANEL);       // 9 x 96
        attn_mma_kernel<<<grid, 256, AK_SMEM>>>();
    }
    // 4) convert attn output, then output projection via HMMA -> d_out
    {
        size_t t4 = (size_t)MROWS * CDIM / 4;
        conv_dual_kernel<<<(unsigned)((t4 + 255) / 256), 256>>>(nullptr, 1, MROWS, CDIM, 0);
        dim3 grid(CDIM / 128, (MROWS + 127) / 128);  // 6 x 65
        gemm_mma_kernel<<<grid, 256, GEMM_SMEM>>>(1, proj_b, out);
    }
}

// round 14
// speedup vs baseline: 2.2997x; 2.0334x over previous
#include <cuda_runtime.h>
#include <cuda_fp16.h>
#include <cstdint>
#include <cstddef>

// Problem constants
#define BATCH 8
#define NSEQ  1032          // 32*32 + 8
#define NSEQP 1088          // padded to 17*64
#define CDIM  768
#define HEADS 12
#define HD    64
#define MROWS (BATCH*NSEQ)  // 8256
#define KVW   1536          // k+v columns
#define KH    768           // fp16 single-pass K
#define NPANEL (BATCH*HEADS) // 96

// Device scratch (static globals — zero-initialized, no runtime allocation).
__device__ float g_kv[(size_t)MROWS * KVW];        // K|V fp32
__device__ float g_att[(size_t)MROWS * CDIM];      // attention output fp32
__device__ __half g_xh  [(size_t)MROWS * KH];      // x fp16
__device__ __half g_atth[(size_t)MROWS * KH];      // attn out fp16
__device__ __half g_wkvh[(size_t)KVW   * KH];      // qkv_w rows 768..2303 fp16
__device__ __half g_wprjh[(size_t)CDIM * KH];      // proj_w fp16
__device__ __half g_kc[(size_t)NPANEL * NSEQP * 64];   // per (b,h): [j][d] K fp16
__device__ __half g_vt[(size_t)NPANEL * 64 * NSEQP];   // per (b,h): [d][j] V^T fp16

// ---------------------------------------------------------------------------
// Helpers (portable PTX: ldmatrix / mma.sync / cp.async)
// ---------------------------------------------------------------------------
__device__ __forceinline__ uint32_t smem_u32(const void* p) {
    uint32_t a;
    asm("{ .reg .u64 t; cvta.to.shared.u64 t, %1; cvt.u32.u64 %0, t; }" : "=r"(a) : "l"(p));
    return a;
}
#define SMEM_SWIZZLE_128B(x) ((x) ^ (((x) >> 3) & 0x70))

#define CP_ASYNC16(sa, ga) \
    asm volatile("cp.async.cg.shared.global [%0], [%1], 16;" :: "r"(sa), "l"(ga) : "memory")
#define CP_COMMIT() asm volatile("cp.async.commit_group;" ::: "memory")
#define CP_WAIT1()  asm volatile("cp.async.wait_group 1;" ::: "memory")
#define CP_WAIT0()  asm volatile("cp.async.wait_group 0;" ::: "memory")

__device__ __forceinline__ void ldsm_x4(uint32_t* r, uint32_t addr) {
    asm volatile("ldmatrix.sync.aligned.m8n8.x4.shared.b16 {%0,%1,%2,%3}, [%4];"
                 : "=r"(r[0]), "=r"(r[1]), "=r"(r[2]), "=r"(r[3]) : "r"(addr));
}

__device__ __forceinline__ void mma_16816(float* c, const uint32_t* a,
                                          uint32_t b0, uint32_t b1) {
    asm volatile("mma.sync.aligned.m16n8k16.row.col.f32.f16.f16.f32 "
                 "{%0,%1,%2,%3}, {%4,%5,%6,%7}, {%8,%9}, {%0,%1,%2,%3};"
                 : "+f"(c[0]), "+f"(c[1]), "+f"(c[2]), "+f"(c[3])
                 : "r"(a[0]), "r"(a[1]), "r"(a[2]), "r"(a[3]), "r"(b0), "r"(b1));
}

// ---------------------------------------------------------------------------
// fp16 conversion. which: 0=g_xh(from x) 1=g_atth(from g_att)
//                         2=g_wkvh(qkv_w rows 768..) 3=g_wprjh(proj_w)
// ---------------------------------------------------------------------------
__global__ __launch_bounds__(256) void conv_half_kernel(
    const float* __restrict__ src_ext, int which, int R, int K, int srow_off)
{
    __half* dst = (which == 0) ? g_xh : (which == 1) ? g_atth
                : (which == 2) ? g_wkvh : g_wprjh;
    const float* src = (which == 1) ? g_att : src_ext;

    size_t total4 = (size_t)R * K / 4;
    size_t idx = (size_t)blockIdx.x * blockDim.x + threadIdx.x;
    if (idx >= total4) return;
    int kq = (int)(idx % (K / 4));
    int r  = (int)(idx / (K / 4));
    float4 v = *(const float4*)(src + (size_t)(srow_off + r) * K + kq * 4);
    __half2 a, b;
    a.x = __float2half_rn(v.x); a.y = __float2half_rn(v.y);
    b.x = __float2half_rn(v.z); b.y = __float2half_rn(v.w);
    __half2* d = (__half2*)(dst + (size_t)r * KH + kq * 4);
    d[0] = a; d[1] = b;
}

// ---------------------------------------------------------------------------
// K/V panel conversion: g_kv fp32 -> g_kc (K fp16 [j][d]) + g_vt (V^T fp16 [d][j])
// ---------------------------------------------------------------------------
__global__ __launch_bounds__(256) void conv_kv_kernel()
{
    __shared__ float vt[64][65];
    const int tid = threadIdx.x;
    const int bh = blockIdx.y, b = bh / HEADS, h = bh % HEADS;
    const int j0 = blockIdx.x * 64;

#pragma unroll
    for (int it = 0; it < 16; it++) {
        int idx = tid + 256 * it;
        int j = idx >> 6, d = idx & 63;
        int gj = j0 + j;
        float vvv = 0.0f;
        if (gj < NSEQ) {
            const float* src = g_kv + ((size_t)b * NSEQ + gj) * KVW + h * HD;
            float kvv = src[d];
            vvv = src[CDIM + d];
            g_kc[((size_t)bh * NSEQP + gj) * 64 + d] = __float2half_rn(kvv);
        }
        vt[j][d] = vvv;
    }
    __syncthreads();
#pragma unroll
    for (int it = 0; it < 16; it++) {
        int idx = tid + 256 * it;
        int d = idx >> 6, j = idx & 63;
        int gj = j0 + j;
        if (gj < NSEQ)
            g_vt[((size_t)bh * 64 + d) * NSEQP + gj] = __float2half_rn(vt[j][d]);
    }
}

// ---------------------------------------------------------------------------
// HMMA fp16 GEMM over K=768: C[m][n] = sum_k A[m][k]*B[n][k] + bias[n]
// 128x128 tile, BK=64, 256 threads = 8 warps (2m x 4n), 12 double-buffered
// stages. Core structure identical to the verified triple-block kernel.
// ---------------------------------------------------------------------------
#define GEMM_SMEM 65536

__global__ __launch_bounds__(256, 2) void gemm_mma_kernel(
    int which, const float* __restrict__ bias, float* __restrict__ outp)
{
    extern __shared__ __align__(128) char smem[];
    const uint32_t sb = smem_u32(smem);

    const __half* __restrict__ A  = which ? g_atth : g_xh;
    const __half* __restrict__ Bw = which ? g_wprjh : g_wkvh;
    float* C = which ? outp : g_kv;
    const int N = which ? CDIM : KVW;

    const int tid  = threadIdx.x;
    const int lane = tid & 31;
    const int w    = tid >> 5;
    const int wm   = w >> 2;
    const int wn   = w & 3;
    const int n0   = blockIdx.x * 128;
    const int m0   = blockIdx.y * 128;

    float acc[4][4][4];
#pragma unroll
    for (int mi = 0; mi < 4; mi++)
#pragma unroll
        for (int ni = 0; ni < 4; ni++)
#pragma unroll
            for (int c = 0; c < 4; c++) acc[mi][ni][c] = 0.0f;

    const int srow = tid >> 3;
    const int q    = tid & 7;

    auto issue_stage = [&](int ch, int buf) {
        const uint32_t sa_base = sb + (uint32_t)buf * 32768u;
        const uint32_t sb_base = sa_base + 16384u;
#pragma unroll
        for (int u = 0; u < 4; u++) {
            const int row = srow + 32 * u;
            int am = m0 + row; if (am > MROWS - 1) am = MROWS - 1;
            const uint32_t so = SMEM_SWIZZLE_128B((uint32_t)(row * 128 + q * 16));
            CP_ASYNC16(sa_base + so, A  + (size_t)am * KH + ch * 64 + q * 8);
            CP_ASYNC16(sb_base + so, Bw + (size_t)(n0 + row) * KH + ch * 64 + q * 8);
        }
        CP_COMMIT();
    };

    const int NSTAGE = KH / 64;      // 12
    issue_stage(0, 0);

    for (int ch = 0; ch < NSTAGE; ch++) {
        const int buf = ch & 1;
        if (ch + 1 < NSTAGE) { issue_stage(ch + 1, buf ^ 1); CP_WAIT1(); }
        else                 { CP_WAIT0(); }
        __syncthreads();

        const uint32_t abase = sb + (uint32_t)buf * 32768u;
        const uint32_t bbase = abase + 16384u;
        const int rsel = lane & 15;
        const int chi  = lane >> 4;

#pragma unroll
        for (int kk = 0; kk < 4; kk++) {
            const int c8 = kk * 2 + chi;
            uint32_t af[4][4], bfr[2][4];
#pragma unroll
            for (int mi = 0; mi < 4; mi++) {
                const int row = wm * 64 + mi * 16 + rsel;
                ldsm_x4(af[mi], abase + SMEM_SWIZZLE_128B((uint32_t)(row * 128 + c8 * 16)));
            }
#pragma unroll
            for (int g = 0; g < 2; g++) {
                const int row = wn * 32 + g * 16 + rsel;
                ldsm_x4(bfr[g], bbase + SMEM_SWIZZLE_128B((uint32_t)(row * 128 + c8 * 16)));
            }
#pragma unroll
            for (int mi = 0; mi < 4; mi++)
#pragma unroll
                for (int ni = 0; ni < 4; ni++) {
                    const int g = ni >> 1, o = ni & 1;
                    mma_16816(acc[mi][ni], af[mi], bfr[g][o], bfr[g][o + 2]);
                }
        }
        __syncthreads();
    }

#pragma unroll
    for (int mi = 0; mi < 4; mi++) {
        const int r0 = m0 + wm * 64 + mi * 16 + (lane >> 2);
        const int r1 = r0 + 8;
#pragma unroll
        for (int ni = 0; ni < 4; ni++) {
            const int col = n0 + wn * 32 + ni * 8 + (lane & 3) * 2;
            const float b0v = bias[col], b1v = bias[col + 1];
            if (r0 < MROWS) {
                float2 v = make_float2(acc[mi][ni][0] + b0v, acc[mi][ni][1] + b1v);
                *(float2*)(C + (size_t)r0 * N + col) = v;
            }
            if (r1 < MROWS) {
                float2 v = make_float2(acc[mi][ni][2] + b0v, acc[mi][ni][3] + b1v);
                *(float2*)(C + (size_t)r1 * N + col) = v;
            }
        }
    }
}

// ---------------------------------------------------------------------------
// Tensor-core flash attention, fp16 single-pass.
// CTA = (b,h) x 128 i-rows, 8 warps x (16 rows x 64 cols). Same verified
// structure as the triple-block version with lo-passes deleted.
// Smem: Ki 16KB | KJ 8KB | VT 8KB | P 16KB | ftab -> 48.5KB.
// ---------------------------------------------------------------------------
#define AK_KI   0
#define AK_KJ   16384
#define AK_VT   24576
#define AK_P    32768
#define AK_FTAB 49152
#define AK_SMEM (49152 + 256)

__global__ __launch_bounds__(256) void attn_mma_kernel()
{
    extern __shared__ __align__(128) char sm[];
    const uint32_t sb = smem_u32(sm);
    float* ftab = (float*)(sm + AK_FTAB);

    const int tid = threadIdx.x, lane = tid & 31, w = tid >> 5;
    const int bh = blockIdx.y, b = bh / HEADS, h = bh % HEADS;
    const int i0 = blockIdx.x * 128;

    if (tid < 63) { float xx = (float)tid - 31.0f; ftab[tid] = __expf(-xx * xx * 0.02f); }

    // Ki tile [128][64] fp16, loaded once
    {
        const int srow = tid >> 3, q = tid & 7;
#pragma unroll
        for (int u = 0; u < 4; u++) {
            int row = srow + 32 * u;
            int gi = i0 + row; if (gi > NSEQ - 1) gi = NSEQ - 1;
            const __half* src = g_kc + ((size_t)bh * NSEQP + gi) * 64 + q * 8;
            uint32_t so = SMEM_SWIZZLE_128B((uint32_t)(row * 128 + q * 16));
            CP_ASYNC16(sb + AK_KI + so, src);
        }
        CP_COMMIT();
    }

    const int rsel = lane & 15, chi = lane >> 4;
    const int rA = w * 16 + (lane >> 2);
    const int iA = i0 + rA, iB = iA + 8;
    const bool okA = (iA >= 8) && (iA < NSEQ);
    const bool okB = (iB >= 8) && (iB < NSEQ);
    const int qiA1 = (iA - 8) >> 5, qiA2 = (iA - 8) & 31;
    const int qiB1 = (iB - 8) >> 5, qiB2 = (iB - 8) & 31;

    float mA = -1e30f, mB = -1e30f, lA = 0.0f, lB = 0.0f;
    float O[8][4];
#pragma unroll
    for (int ni = 0; ni < 8; ni++)
#pragma unroll
        for (int c = 0; c < 4; c++) O[ni][c] = 0.0f;

    const float scale = 0.125f;

    for (int jt = 0; jt < NSEQP; jt += 64) {
        __syncthreads();   // prior tile fully consumed by all warps
        {
            const int srow = tid >> 3, q = tid & 7;
#pragma unroll
            for (int u = 0; u < 2; u++) {
                int row = srow + 32 * u;
                const __half* sk = g_kc + ((size_t)bh * NSEQP + jt + row) * 64 + q * 8;
                const __half* sv = g_vt + ((size_t)bh * 64 + row) * NSEQP + jt + q * 8;
                uint32_t so = SMEM_SWIZZLE_128B((uint32_t)(row * 128 + q * 16));
                CP_ASYNC16(sb + AK_KJ + so, sk);
                CP_ASYNC16(sb + AK_VT + so, sv);
            }
            CP_COMMIT(); CP_WAIT0();
        }
        __syncthreads();

        // ---- S = Ki.Kj^T (single fp16 pass) ----
        float s[8][4];
#pragma unroll
        for (int ni = 0; ni < 8; ni++)
#pragma unroll
            for (int c = 0; c < 4; c++) s[ni][c] = 0.0f;

#pragma unroll
        for (int kk = 0; kk < 4; kk++) {
            const int c8 = kk * 2 + chi;
            uint32_t af[4], bfr[4][4];
            ldsm_x4(af, sb + AK_KI +
                    SMEM_SWIZZLE_128B((uint32_t)((w * 16 + rsel) * 128 + c8 * 16)));
#pragma unroll
            for (int g = 0; g < 4; g++)
                ldsm_x4(bfr[g], sb + AK_KJ +
                        SMEM_SWIZZLE_128B((uint32_t)((g * 16 + rsel) * 128 + c8 * 16)));
#pragma unroll
            for (int ni = 0; ni < 8; ni++)
                mma_16816(s[ni], af, bfr[ni >> 1][ni & 1], bfr[ni >> 1][(ni & 1) + 2]);
        }

        // ---- scale + gaussian bias + tail mask ----
#pragma unroll
        for (int ni = 0; ni < 8; ni++) {
            const int jbase = jt + ni * 8 + ((lane & 3) << 1);
#pragma unroll
            for (int c = 0; c < 4; c++) {
                const int j = jbase + (c & 1);
                float val = s[ni][c] * scale;
                const bool ok = (c < 2) ? okA : okB;
                const int q1 = (c < 2) ? qiA1 : qiB1;
                const int q2 = (c < 2) ? qiA2 : qiB2;
                if (j < NSEQ) {
                    if (ok && j >= 8)
                        val += ftab[q1 - ((j - 8) >> 5) + 31] * ftab[q2 - ((j - 8) & 31) + 31];
                } else val = -1e30f;
                s[ni][c] = val;
            }
        }

        // ---- online softmax ----
        float tA = -1e30f, tB = -1e30f;
#pragma unroll
        for (int ni = 0; ni < 8; ni++) {
            tA = fmaxf(tA, fmaxf(s[ni][0], s[ni][1]));
            tB = fmaxf(tB, fmaxf(s[ni][2], s[ni][3]));
        }
        tA = fmaxf(tA, __shfl_xor_sync(0xffffffffu, tA, 1));
        tA = fmaxf(tA, __shfl_xor_sync(0xffffffffu, tA, 2));
        tB = fmaxf(tB, __shfl_xor_sync(0xffffffffu, tB, 1));
        tB = fmaxf(tB, __shfl_xor_sync(0xffffffffu, tB, 2));
        const float mnA = fmaxf(mA, tA), mnB = fmaxf(mB, tB);
        const float cA = __expf(mA - mnA), cB = __expf(mB - mnB);
        float rsA = 0.0f, rsB = 0.0f;
#pragma unroll
        for (int ni = 0; ni < 8; ni++) {
            s[ni][0] = __expf(s[ni][0] - mnA); rsA += s[ni][0];
            s[ni][1] = __expf(s[ni][1] - mnA); rsA += s[ni][1];
            s[ni][2] = __expf(s[ni][2] - mnB); rsB += s[ni][2];
            s[ni][3] = __expf(s[ni][3] - mnB); rsB += s[ni][3];
        }
        rsA += __shfl_xor_sync(0xffffffffu, rsA, 1);
        rsA += __shfl_xor_sync(0xffffffffu, rsA, 2);
        rsB += __shfl_xor_sync(0xffffffffu, rsB, 1);
        rsB += __shfl_xor_sync(0xffffffffu, rsB, 2);
        lA = lA * cA + rsA; lB = lB * cB + rsB;
        mA = mnA; mB = mnB;

        // ---- P -> smem (fp16, warp-private rows) + O rescale ----
        const uint32_t rowoffA = (uint32_t)((w * 16 + (lane >> 2)) * 128 + (lane & 3) * 4);
        const uint32_t rowoffB = rowoffA + 8 * 128;
#pragma unroll
        for (int ni = 0; ni < 8; ni++) {
            O[ni][0] *= cA; O[ni][1] *= cA; O[ni][2] *= cB; O[ni][3] *= cB;

            __half2 pv;
            pv.x = __float2half_rn(s[ni][0]); pv.y = __float2half_rn(s[ni][1]);
            *(__half2*)(sm + AK_P + SMEM_SWIZZLE_128B(rowoffA + ni * 16)) = pv;

            __half2 pv2;
            pv2.x = __float2half_rn(s[ni][2]); pv2.y = __float2half_rn(s[ni][3]);
            *(__half2*)(sm + AK_P + SMEM_SWIZZLE_128B(rowoffB + ni * 16)) = pv2;
        }
        __syncwarp();

        // ---- O += P.V (single fp16 pass) ----
#pragma unroll
        for (int kk = 0; kk < 4; kk++) {
            const int c8 = kk * 2 + chi;
            uint32_t af[4], bfr[4][4];
            ldsm_x4(af, sb + AK_P +
                    SMEM_SWIZZLE_128B((uint32_t)((w * 16 + rsel) * 128 + c8 * 16)));
#pragma unroll
            for (int g = 0; g < 4; g++)
                ldsm_x4(bfr[g], sb + AK_VT +
                        SMEM_SWIZZLE_128B((uint32_t)((g * 16 + rsel) * 128 + c8 * 16)));
#pragma unroll
            for (int ni = 0; ni < 8; ni++)
                mma_16816(O[ni], af, bfr[ni >> 1][ni & 1], bfr[ni >> 1][(ni & 1) + 2]);
        }
    }

    // ---- epilogue: normalize, write fp32 g_att (coalesced float2) ----
    const float invA = 1.0f / lA, invB = 1.0f / lB;
#pragma unroll
    for (int ni = 0; ni < 8; ni++) {
        const int d = ni * 8 + ((lane & 3) << 1);
        if (iA < NSEQ) {
            float2 v = make_float2(O[ni][0] * invA, O[ni][1] * invA);
            *(float2*)(g_att + ((size_t)(b * NSEQ + iA)) * CDIM + h * HD + d) = v;
        }
        if (iB < NSEQ) {
            float2 v = make_float2(O[ni][2] * invB, O[ni][3] * invB);
            *(float2*)(g_att + ((size_t)(b * NSEQ + iB)) * CDIM + h * HD + d) = v;
        }
    }
}

// ---------------------------------------------------------------------------
extern "C" void kernel_launch(void* const* d_in, const int* in_sizes, int n_in,
                              void* d_out, int out_size)
{
    const float* x = nullptr;
    const float* qkv_w = nullptr;
    const float* qkv_b = nullptr;
    const float* proj_w = nullptr;
    const float* proj_b = nullptr;
    for (int i = 0; i < n_in; i++) {
        switch (in_sizes[i]) {
            case 6340608: x      = (const float*)d_in[i]; break;
            case 1769472: qkv_w  = (const float*)d_in[i]; break;
            case 2304:    qkv_b  = (const float*)d_in[i]; break;
            case 589824:  proj_w = (const float*)d_in[i]; break;
            case 768:     proj_b = (const float*)d_in[i]; break;
        }
    }
    float* out = (float*)d_out;

    cudaFuncSetAttribute(gemm_mma_kernel, cudaFuncAttributeMaxDynamicSharedMemorySize, GEMM_SMEM);
    cudaFuncSetAttribute(attn_mma_kernel, cudaFuncAttributeMaxDynamicSharedMemorySize, AK_SMEM);

    // conversions: x, W_kv, W_proj -> fp16
    {
        size_t t4 = (size_t)MROWS * CDIM / 4;
        conv_half_kernel<<<(unsigned)((t4 + 255) / 256), 256>>>(x, 0, MROWS, CDIM, 0);
        t4 = (size_t)KVW * CDIM / 4;
        conv_half_kernel<<<(unsigned)((t4 + 255) / 256), 256>>>(qkv_w, 2, KVW, CDIM, CDIM);
        t4 = (size_t)CDIM * CDIM / 4;
        conv_half_kernel<<<(unsigned)((t4 + 255) / 256), 256>>>(proj_w, 3, CDIM, CDIM, 0);
    }
    // 1) K,V projection via fp16 HMMA -> g_kv (fp32)
    {
        dim3 grid(KVW / 128, (MROWS + 127) / 128);   // 12 x 65
        gemm_mma_kernel<<<grid, 256, GEMM_SMEM>>>(0, qkv_b + CDIM, nullptr);
    }
    // 2) K/V panel conversion (fp16, V transposed)
    {
        dim3 grid(17, NPANEL);                       // 17 x 96
        conv_kv_kernel<<<grid, 256>>>();
    }
    // 3) tensor-core flash attention -> g_att (fp32)
    {
        dim3 grid((NSEQ + 127) / 128, NPANEL);       // 9 x 96
        attn_mma_kernel<<<grid, 256, AK_SMEM>>>();
    }
    // 4) convert attn output, then output projection via fp16 HMMA -> d_out
    {
        size_t t4 = (size_t)MROWS * CDIM / 4;
        conv_half_kernel<<<(unsigned)((t4 + 255) / 256), 256>>>(nullptr, 1, MROWS, CDIM, 0);
        dim3 grid(CDIM / 128, (MROWS + 127) / 128);  // 6 x 65
        gemm_mma_kernel<<<grid, 256, GEMM_SMEM>>>(1, proj_b, out);
    }
}

// round 15
// speedup vs baseline: 2.6413x; 1.1485x over previous
#include <cuda_runtime.h>
#include <cuda_fp16.h>
#include <cstdint>
#include <cstddef>

// Problem constants
#define BATCH 8
#define NSEQ  1032          // 32*32 + 8
#define NSEQP 1088          // padded to 17*64
#define CDIM  768
#define HEADS 12
#define HD    64
#define MROWS (BATCH*NSEQ)  // 8256
#define KVW   1536          // k+v columns
#define KH    768           // fp16 single-pass K
#define NPANEL (BATCH*HEADS) // 96

// Device scratch (static globals — zero-initialized, no runtime allocation).
__device__ float g_kv[(size_t)MROWS * KVW];        // K|V fp32
__device__ __half g_xh  [(size_t)MROWS * KH];      // x fp16
__device__ __half g_atth[(size_t)MROWS * KH];      // attn out fp16 (written by attn epilogue)
__device__ __half g_wkvh[(size_t)KVW   * KH];      // qkv_w rows 768..2303 fp16
__device__ __half g_wprjh[(size_t)CDIM * KH];      // proj_w fp16
__device__ __half g_kc[(size_t)NPANEL * NSEQP * 64];   // per (b,h): [j][d] K fp16
__device__ __half g_vt[(size_t)NPANEL * 64 * NSEQP];   // per (b,h): [d][j] V^T fp16

// ---------------------------------------------------------------------------
// Helpers (portable PTX: ldmatrix / mma.sync / cp.async)
// ---------------------------------------------------------------------------
__device__ __forceinline__ uint32_t smem_u32(const void* p) {
    uint32_t a;
    asm("{ .reg .u64 t; cvta.to.shared.u64 t, %1; cvt.u32.u64 %0, t; }" : "=r"(a) : "l"(p));
    return a;
}
#define SMEM_SWIZZLE_128B(x) ((x) ^ (((x) >> 3) & 0x70))

#define CP_ASYNC16(sa, ga) \
    asm volatile("cp.async.cg.shared.global [%0], [%1], 16;" :: "r"(sa), "l"(ga) : "memory")
#define CP_COMMIT() asm volatile("cp.async.commit_group;" ::: "memory")
#define CP_WAIT1()  asm volatile("cp.async.wait_group 1;" ::: "memory")
#define CP_WAIT0()  asm volatile("cp.async.wait_group 0;" ::: "memory")

__device__ __forceinline__ void ldsm_x4(uint32_t* r, uint32_t addr) {
    asm volatile("ldmatrix.sync.aligned.m8n8.x4.shared.b16 {%0,%1,%2,%3}, [%4];"
                 : "=r"(r[0]), "=r"(r[1]), "=r"(r[2]), "=r"(r[3]) : "r"(addr));
}

__device__ __forceinline__ void mma_16816(float* c, const uint32_t* a,
                                          uint32_t b0, uint32_t b1) {
    asm volatile("mma.sync.aligned.m16n8k16.row.col.f32.f16.f16.f32 "
                 "{%0,%1,%2,%3}, {%4,%5,%6,%7}, {%8,%9}, {%0,%1,%2,%3};"
                 : "+f"(c[0]), "+f"(c[1]), "+f"(c[2]), "+f"(c[3])
                 : "r"(a[0]), "r"(a[1]), "r"(a[2]), "r"(a[3]), "r"(b0), "r"(b1));
}

// ---------------------------------------------------------------------------
// fp16 conversion. which: 0=g_xh(from x) 2=g_wkvh(qkv_w rows 768..) 3=g_wprjh(proj_w)
// ---------------------------------------------------------------------------
__global__ __launch_bounds__(256) void conv_half_kernel(
    const float* __restrict__ src, int which, int R, int K, int srow_off)
{
    __half* dst = (which == 0) ? g_xh : (which == 2) ? g_wkvh : g_wprjh;

    size_t total4 = (size_t)R * K / 4;
    size_t idx = (size_t)blockIdx.x * blockDim.x + threadIdx.x;
    if (idx >= total4) return;
    int kq = (int)(idx % (K / 4));
    int r  = (int)(idx / (K / 4));
    float4 v = *(const float4*)(src + (size_t)(srow_off + r) * K + kq * 4);
    __half2 a, b;
    a.x = __float2half_rn(v.x); a.y = __float2half_rn(v.y);
    b.x = __float2half_rn(v.z); b.y = __float2half_rn(v.w);
    __half2* d = (__half2*)(dst + (size_t)r * KH + kq * 4);
    d[0] = a; d[1] = b;
}

// ---------------------------------------------------------------------------
// K/V panel conversion: g_kv fp32 -> g_kc (K fp16 [j][d]) + g_vt (V^T fp16 [d][j])
// ---------------------------------------------------------------------------
__global__ __launch_bounds__(256) void conv_kv_kernel()
{
    __shared__ float vt[64][65];
    const int tid = threadIdx.x;
    const int bh = blockIdx.y, b = bh / HEADS, h = bh % HEADS;
    const int j0 = blockIdx.x * 64;

#pragma unroll
    for (int it = 0; it < 16; it++) {
        int idx = tid + 256 * it;
        int j = idx >> 6, d = idx & 63;
        int gj = j0 + j;
        float vvv = 0.0f;
        if (gj < NSEQ) {
            const float* src = g_kv + ((size_t)b * NSEQ + gj) * KVW + h * HD;
            float kvv = src[d];
            vvv = src[CDIM + d];
            g_kc[((size_t)bh * NSEQP + gj) * 64 + d] = __float2half_rn(kvv);
        }
        vt[j][d] = vvv;
    }
    __syncthreads();
#pragma unroll
    for (int it = 0; it < 16; it++) {
        int idx = tid + 256 * it;
        int d = idx >> 6, j = idx & 63;
        int gj = j0 + j;
        if (gj < NSEQ)
            g_vt[((size_t)bh * 64 + d) * NSEQP + gj] = __float2half_rn(vt[j][d]);
    }
}

// ---------------------------------------------------------------------------
// HMMA fp16 GEMM over K=768 (verified R14: 67us for kv).
// ---------------------------------------------------------------------------
#define GEMM_SMEM 65536

__global__ __launch_bounds__(256, 2) void gemm_mma_kernel(
    int which, const float* __restrict__ bias, float* __restrict__ outp)
{
    extern __shared__ __align__(128) char smem[];
    const uint32_t sb = smem_u32(smem);

    const __half* __restrict__ A  = which ? g_atth : g_xh;
    const __half* __restrict__ Bw = which ? g_wprjh : g_wkvh;
    float* C = which ? outp : g_kv;
    const int N = which ? CDIM : KVW;

    const int tid  = threadIdx.x;
    const int lane = tid & 31;
    const int w    = tid >> 5;
    const int wm   = w >> 2;
    const int wn   = w & 3;
    const int n0   = blockIdx.x * 128;
    const int m0   = blockIdx.y * 128;

    float acc[4][4][4];
#pragma unroll
    for (int mi = 0; mi < 4; mi++)
#pragma unroll
        for (int ni = 0; ni < 4; ni++)
#pragma unroll
            for (int c = 0; c < 4; c++) acc[mi][ni][c] = 0.0f;

    const int srow = tid >> 3;
    const int q    = tid & 7;

    auto issue_stage = [&](int ch, int buf) {
        const uint32_t sa_base = sb + (uint32_t)buf * 32768u;
        const uint32_t sb_base = sa_base + 16384u;
#pragma unroll
        for (int u = 0; u < 4; u++) {
            const int row = srow + 32 * u;
            int am = m0 + row; if (am > MROWS - 1) am = MROWS - 1;
            const uint32_t so = SMEM_SWIZZLE_128B((uint32_t)(row * 128 + q * 16));
            CP_ASYNC16(sa_base + so, A  + (size_t)am * KH + ch * 64 + q * 8);
            CP_ASYNC16(sb_base + so, Bw + (size_t)(n0 + row) * KH + ch * 64 + q * 8);
        }
        CP_COMMIT();
    };

    const int NSTAGE = KH / 64;      // 12
    issue_stage(0, 0);

    for (int ch = 0; ch < NSTAGE; ch++) {
        const int buf = ch & 1;
        if (ch + 1 < NSTAGE) { issue_stage(ch + 1, buf ^ 1); CP_WAIT1(); }
        else                 { CP_WAIT0(); }
        __syncthreads();

        const uint32_t abase = sb + (uint32_t)buf * 32768u;
        const uint32_t bbase = abase + 16384u;
        const int rsel = lane & 15;
        const int chi  = lane >> 4;

#pragma unroll
        for (int kk = 0; kk < 4; kk++) {
            const int c8 = kk * 2 + chi;
            uint32_t af[4][4], bfr[2][4];
#pragma unroll
            for (int mi = 0; mi < 4; mi++) {
                const int row = wm * 64 + mi * 16 + rsel;
                ldsm_x4(af[mi], abase + SMEM_SWIZZLE_128B((uint32_t)(row * 128 + c8 * 16)));
            }
#pragma unroll
            for (int g = 0; g < 2; g++) {
                const int row = wn * 32 + g * 16 + rsel;
                ldsm_x4(bfr[g], bbase + SMEM_SWIZZLE_128B((uint32_t)(row * 128 + c8 * 16)));
            }
#pragma unroll
            for (int mi = 0; mi < 4; mi++)
#pragma unroll
                for (int ni = 0; ni < 4; ni++) {
                    const int g = ni >> 1, o = ni & 1;
                    mma_16816(acc[mi][ni], af[mi], bfr[g][o], bfr[g][o + 2]);
                }
        }
        __syncthreads();
    }

#pragma unroll
    for (int mi = 0; mi < 4; mi++) {
        const int r0 = m0 + wm * 64 + mi * 16 + (lane >> 2);
        const int r1 = r0 + 8;
#pragma unroll
        for (int ni = 0; ni < 4; ni++) {
            const int col = n0 + wn * 32 + ni * 8 + (lane & 3) * 2;
            const float b0v = bias[col], b1v = bias[col + 1];
            if (r0 < MROWS) {
                float2 v = make_float2(acc[mi][ni][0] + b0v, acc[mi][ni][1] + b1v);
                *(float2*)(C + (size_t)r0 * N + col) = v;
            }
            if (r1 < MROWS) {
                float2 v = make_float2(acc[mi][ni][2] + b0v, acc[mi][ni][3] + b1v);
                *(float2*)(C + (size_t)r1 * N + col) = v;
            }
        }
    }
}

// ---------------------------------------------------------------------------
// Tensor-core flash attention, fp16 single-pass (verified R14 structure).
// Changes this round: (a) launch_bounds(256,2) — smem 48.5KB allows 2 CTAs/SM,
// cap regs to 128 so RF does too; (b) epilogue writes g_atth fp16 directly
// (same rounding as the deleted conv kernel; coalesced half2 stores).
// ---------------------------------------------------------------------------
#define AK_KI   0
#define AK_KJ   16384
#define AK_VT   24576
#define AK_P    32768
#define AK_FTAB 49152
#define AK_SMEM (49152 + 256)

__global__ __launch_bounds__(256, 2) void attn_mma_kernel()
{
    extern __shared__ __align__(128) char sm[];
    const uint32_t sb = smem_u32(sm);
    float* ftab = (float*)(sm + AK_FTAB);

    const int tid = threadIdx.x, lane = tid & 31, w = tid >> 5;
    const int bh = blockIdx.y, b = bh / HEADS, h = bh % HEADS;
    const int i0 = blockIdx.x * 128;

    if (tid < 63) { float xx = (float)tid - 31.0f; ftab[tid] = __expf(-xx * xx * 0.02f); }

    // Ki tile [128][64] fp16, loaded once
    {
        const int srow = tid >> 3, q = tid & 7;
#pragma unroll
        for (int u = 0; u < 4; u++) {
            int row = srow + 32 * u;
            int gi = i0 + row; if (gi > NSEQ - 1) gi = NSEQ - 1;
            const __half* src = g_kc + ((size_t)bh * NSEQP + gi) * 64 + q * 8;
            uint32_t so = SMEM_SWIZZLE_128B((uint32_t)(row * 128 + q * 16));
            CP_ASYNC16(sb + AK_KI + so, src);
        }
        CP_COMMIT();
    }

    const int rsel = lane & 15, chi = lane >> 4;
    const int rA = w * 16 + (lane >> 2);
    const int iA = i0 + rA, iB = iA + 8;
    const bool okA = (iA >= 8) && (iA < NSEQ);
    const bool okB = (iB >= 8) && (iB < NSEQ);
    const int qiA1 = (iA - 8) >> 5, qiA2 = (iA - 8) & 31;
    const int qiB1 = (iB - 8) >> 5, qiB2 = (iB - 8) & 31;

    float mA = -1e30f, mB = -1e30f, lA = 0.0f, lB = 0.0f;
    float O[8][4];
#pragma unroll
    for (int ni = 0; ni < 8; ni++)
#pragma unroll
        for (int c = 0; c < 4; c++) O[ni][c] = 0.0f;

    const float scale = 0.125f;

    for (int jt = 0; jt < NSEQP; jt += 64) {
        __syncthreads();   // prior tile fully consumed by all warps
        {
            const int srow = tid >> 3, q = tid & 7;
#pragma unroll
            for (int u = 0; u < 2; u++) {
                int row = srow + 32 * u;
                const __half* sk = g_kc + ((size_t)bh * NSEQP + jt + row) * 64 + q * 8;
                const __half* sv = g_vt + ((size_t)bh * 64 + row) * NSEQP + jt + q * 8;
                uint32_t so = SMEM_SWIZZLE_128B((uint32_t)(row * 128 + q * 16));
                CP_ASYNC16(sb + AK_KJ + so, sk);
                CP_ASYNC16(sb + AK_VT + so, sv);
            }
            CP_COMMIT(); CP_WAIT0();
        }
        __syncthreads();

        // ---- S = Ki.Kj^T (single fp16 pass) ----
        float s[8][4];
#pragma unroll
        for (int ni = 0; ni < 8; ni++)
#pragma unroll
            for (int c = 0; c < 4; c++) s[ni][c] = 0.0f;

#pragma unroll
        for (int kk = 0; kk < 4; kk++) {
            const int c8 = kk * 2 + chi;
            uint32_t af[4], bfr[4][4];
            ldsm_x4(af, sb + AK_KI +
                    SMEM_SWIZZLE_128B((uint32_t)((w * 16 + rsel) * 128 + c8 * 16)));
#pragma unroll
            for (int g = 0; g < 4; g++)
                ldsm_x4(bfr[g], sb + AK_KJ +
                        SMEM_SWIZZLE_128B((uint32_t)((g * 16 + rsel) * 128 + c8 * 16)));
#pragma unroll
            for (int ni = 0; ni < 8; ni++)
                mma_16816(s[ni], af, bfr[ni >> 1][ni & 1], bfr[ni >> 1][(ni & 1) + 2]);
        }

        // ---- scale + gaussian bias + tail mask ----
#pragma unroll
        for (int ni = 0; ni < 8; ni++) {
            const int jbase = jt + ni * 8 + ((lane & 3) << 1);
#pragma unroll
            for (int c = 0; c < 4; c++) {
                const int j = jbase + (c & 1);
                float val = s[ni][c] * scale;
                const bool ok = (c < 2) ? okA : okB;
                const int q1 = (c < 2) ? qiA1 : qiB1;
                const int q2 = (c < 2) ? qiA2 : qiB2;
                if (j < NSEQ) {
                    if (ok && j >= 8)
                        val += ftab[q1 - ((j - 8) >> 5) + 31] * ftab[q2 - ((j - 8) & 31) + 31];
                } else val = -1e30f;
                s[ni][c] = val;
            }
        }

        // ---- online softmax ----
        float tA = -1e30f, tB = -1e30f;
#pragma unroll
        for (int ni = 0; ni < 8; ni++) {
            tA = fmaxf(tA, fmaxf(s[ni][0], s[ni][1]));
            tB = fmaxf(tB, fmaxf(s[ni][2], s[ni][3]));
        }
        tA = fmaxf(tA, __shfl_xor_sync(0xffffffffu, tA, 1));
        tA = fmaxf(tA, __shfl_xor_sync(0xffffffffu, tA, 2));
        tB = fmaxf(tB, __shfl_xor_sync(0xffffffffu, tB, 1));
        tB = fmaxf(tB, __shfl_xor_sync(0xffffffffu, tB, 2));
        const float mnA = fmaxf(mA, tA), mnB = fmaxf(mB, tB);
        const float cA = __expf(mA - mnA), cB = __expf(mB - mnB);
        float rsA = 0.0f, rsB = 0.0f;
#pragma unroll
        for (int ni = 0; ni < 8; ni++) {
            s[ni][0] = __expf(s[ni][0] - mnA); rsA += s[ni][0];
            s[ni][1] = __expf(s[ni][1] - mnA); rsA += s[ni][1];
            s[ni][2] = __expf(s[ni][2] - mnB); rsB += s[ni][2];
            s[ni][3] = __expf(s[ni][3] - mnB); rsB += s[ni][3];
        }
        rsA += __shfl_xor_sync(0xffffffffu, rsA, 1);
        rsA += __shfl_xor_sync(0xffffffffu, rsA, 2);
        rsB += __shfl_xor_sync(0xffffffffu, rsB, 1);
        rsB += __shfl_xor_sync(0xffffffffu, rsB, 2);
        lA = lA * cA + rsA; lB = lB * cB + rsB;
        mA = mnA; mB = mnB;

        // ---- P -> smem (fp16, warp-private rows) + O rescale ----
        const uint32_t rowoffA = (uint32_t)((w * 16 + (lane >> 2)) * 128 + (lane & 3) * 4);
        const uint32_t rowoffB = rowoffA + 8 * 128;
#pragma unroll
        for (int ni = 0; ni < 8; ni++) {
            O[ni][0] *= cA; O[ni][1] *= cA; O[ni][2] *= cB; O[ni][3] *= cB;

            __half2 pv;
            pv.x = __float2half_rn(s[ni][0]); pv.y = __float2half_rn(s[ni][1]);
            *(__half2*)(sm + AK_P + SMEM_SWIZZLE_128B(rowoffA + ni * 16)) = pv;

            __half2 pv2;
            pv2.x = __float2half_rn(s[ni][2]); pv2.y = __float2half_rn(s[ni][3]);
            *(__half2*)(sm + AK_P + SMEM_SWIZZLE_128B(rowoffB + ni * 16)) = pv2;
        }
        __syncwarp();

        // ---- O += P.V (single fp16 pass) ----
#pragma unroll
        for (int kk = 0; kk < 4; kk++) {
            const int c8 = kk * 2 + chi;
            uint32_t af[4], bfr[4][4];
            ldsm_x4(af, sb + AK_P +
                    SMEM_SWIZZLE_128B((uint32_t)((w * 16 + rsel) * 128 + c8 * 16)));
#pragma unroll
            for (int g = 0; g < 4; g++)
                ldsm_x4(bfr[g], sb + AK_VT +
                        SMEM_SWIZZLE_128B((uint32_t)((g * 16 + rsel) * 128 + c8 * 16)));
#pragma unroll
            for (int ni = 0; ni < 8; ni++)
                mma_16816(O[ni], af, bfr[ni >> 1][ni & 1], bfr[ni >> 1][(ni & 1) + 2]);
        }
    }

    // ---- epilogue: normalize, write g_atth fp16 directly (coalesced half2) ----
    const float invA = 1.0f / lA, invB = 1.0f / lB;
#pragma unroll
    for (int ni = 0; ni < 8; ni++) {
        const int d = ni * 8 + ((lane & 3) << 1);
        if (iA < NSEQ) {
            __half2 v;
            v.x = __float2half_rn(O[ni][0] * invA);
            v.y = __float2half_rn(O[ni][1] * invA);
            *(__half2*)(g_atth + (size_t)(b * NSEQ + iA) * KH + h * HD + d) = v;
        }
        if (iB < NSEQ) {
            __half2 v;
            v.x = __float2half_rn(O[ni][2] * invB);
            v.y = __float2half_rn(O[ni][3] * invB);
            *(__half2*)(g_atth + (size_t)(b * NSEQ + iB) * KH + h * HD + d) = v;
        }
    }
}

// ---------------------------------------------------------------------------
extern "C" void kernel_launch(void* const* d_in, const int* in_sizes, int n_in,
                              void* d_out, int out_size)
{
    const float* x = nullptr;
    const float* qkv_w = nullptr;
    const float* qkv_b = nullptr;
    const float* proj_w = nullptr;
    const float* proj_b = nullptr;
    for (int i = 0; i < n_in; i++) {
        switch (in_sizes[i]) {
            case 6340608: x      = (const float*)d_in[i]; break;
            case 1769472: qkv_w  = (const float*)d_in[i]; break;
            case 2304:    qkv_b  = (const float*)d_in[i]; break;
            case 589824:  proj_w = (const float*)d_in[i]; break;
            case 768:     proj_b = (const float*)d_in[i]; break;
        }
    }
    float* out = (float*)d_out;

    cudaFuncSetAttribute(gemm_mma_kernel, cudaFuncAttributeMaxDynamicSharedMemorySize, GEMM_SMEM);
    cudaFuncSetAttribute(attn_mma_kernel, cudaFuncAttributeMaxDynamicSharedMemorySize, AK_SMEM);

    // conversions: x, W_kv, W_proj -> fp16
    {
        size_t t4 = (size_t)MROWS * CDIM / 4;
        conv_half_kernel<<<(unsigned)((t4 + 255) / 256), 256>>>(x, 0, MROWS, CDIM, 0);
        t4 = (size_t)KVW * CDIM / 4;
        conv_half_kernel<<<(unsigned)((t4 + 255) / 256), 256>>>(qkv_w, 2, KVW, CDIM, CDIM);
        t4 = (size_t)CDIM * CDIM / 4;
        conv_half_kernel<<<(unsigned)((t4 + 255) / 256), 256>>>(proj_w, 3, CDIM, CDIM, 0);
    }
    // 1) K,V projection via fp16 HMMA -> g_kv (fp32)
    {
        dim3 grid(KVW / 128, (MROWS + 127) / 128);   // 12 x 65
        gemm_mma_kernel<<<grid, 256, GEMM_SMEM>>>(0, qkv_b + CDIM, nullptr);
    }
    // 2) K/V panel conversion (fp16, V transposed)
    {
        dim3 grid(17, NPANEL);                       // 17 x 96
        conv_kv_kernel<<<grid, 256>>>();
    }
    // 3) tensor-core flash attention -> g_atth (fp16, direct)
    {
        dim3 grid((NSEQ + 127) / 128, NPANEL);       // 9 x 96
        attn_mma_kernel<<<grid, 256, AK_SMEM>>>();
    }
    // 4) output projection via fp16 HMMA -> d_out
    {
        dim3 grid(CDIM / 128, (MROWS + 127) / 128);  // 6 x 65
        gemm_mma_kernel<<<grid, 256, GEMM_SMEM>>>(1, proj_b, out);
    }
}